// round 7
// baseline (speedup 1.0000x reference)
#include <cuda_runtime.h>
#include <cuda_fp16.h>
#include <math.h>
#include <cstdint>

#define SEQ    512
#define DQ     1024
#define MTOK   4096
#define SCALE  0.044194173824159216f   // 1/sqrt(512)
#define NEG    -4.4194174e18f          // -1e20 * SCALE

// Scratch (device globals; no allocation allowed)
__device__ __half g_xq[MTOK * DQ];   // converted inputs
__device__ __half g_xk[MTOK * DQ];
__device__ __half g_xv[MTOK * DQ];
__device__ __half g_wq[DQ * DQ];     // converted weights
__device__ __half g_wk[DQ * DQ];
__device__ __half g_wv[DQ * DQ];
__device__ __half g_wo[DQ * DQ];
__device__ __half g_q [MTOK * DQ];   // projections
__device__ __half g_k [MTOK * DQ];
__device__ __half g_v [MTOK * DQ];
__device__ __half g_ao[MTOK * DQ];   // attention output

// ---------------------------------------------------------------------------
// helpers
// ---------------------------------------------------------------------------
__device__ __forceinline__ void mma_f16(float* c, const unsigned* a, const unsigned* b) {
    asm volatile(
        "mma.sync.aligned.m16n8k16.row.col.f32.f16.f16.f32 "
        "{%0,%1,%2,%3}, {%4,%5,%6,%7}, {%8,%9}, {%0,%1,%2,%3};\n"
        : "+f"(c[0]), "+f"(c[1]), "+f"(c[2]), "+f"(c[3])
        : "r"(a[0]), "r"(a[1]), "r"(a[2]), "r"(a[3]), "r"(b[0]), "r"(b[1]));
}
__device__ __forceinline__ void ldm_x4(unsigned* r, uint32_t addr) {
    asm volatile("ldmatrix.sync.aligned.m8n8.x4.shared.b16 {%0,%1,%2,%3}, [%4];"
                 : "=r"(r[0]), "=r"(r[1]), "=r"(r[2]), "=r"(r[3]) : "r"(addr));
}
__device__ __forceinline__ uint32_t smem_u32(const void* p) {
    uint32_t a;
    asm("{ .reg .u64 t; cvta.to.shared.u64 t, %1; cvt.u32.u64 %0, t; }" : "=r"(a) : "l"(p));
    return a;
}
__device__ __forceinline__ void cp16(uint32_t s, const void* g) {
    asm volatile("cp.async.cg.shared.global [%0], [%1], 16;" :: "r"(s), "l"(g));
}
#define CP_COMMIT() asm volatile("cp.async.commit_group;" ::: "memory")
__device__ __forceinline__ unsigned pack_h2(float x, float y) {
    __half2 h = __floats2half2_rn(x, y);
    return *(unsigned*)&h;
}

// ---------------------------------------------------------------------------
// f32 -> f16 conversion of inputs and weights, one pass.
// ---------------------------------------------------------------------------
__global__ __launch_bounds__(256) void cvt_kernel(
    const float* __restrict__ q, const float* __restrict__ k, const float* __restrict__ v,
    const float* __restrict__ wv, const float* __restrict__ wk,
    const float* __restrict__ wq, const float* __restrict__ wo)
{
    const long stride = (long)gridDim.x * blockDim.x;
    for (long i = (long)blockIdx.x * blockDim.x + threadIdx.x; i < 4194304; i += stride) {
        const float* src; __half* dst; long off;
        if (i < 3145728) {
            int which = (int)(i >> 20);
            off = i & 1048575;
            src = which == 0 ? q : which == 1 ? k : v;
            dst = which == 0 ? g_xq : which == 1 ? g_xk : g_xv;
        } else {
            long j = i - 3145728;
            int which = (int)(j >> 18);
            off = j & 262143;
            src = which == 0 ? wv : which == 1 ? wk : which == 2 ? wq : wo;
            dst = which == 0 ? g_wv : which == 1 ? g_wk : which == 2 ? g_wq : g_wo;
        }
        float4 val = ((const float4*)src)[off];
        uint2 h;
        h.x = pack_h2(val.x, val.y);
        h.y = pack_h2(val.z, val.w);
        ((uint2*)dst)[off] = h;
    }
}

// ---------------------------------------------------------------------------
// Pipelined fp16 GEMM: C[4096][1024] = A @ W^T + bias.
// 128x128 tile, BK=64, 3-stage cp.async ring, 8 warps (2x4), 64x32 warp tile.
// Fragments via ldmatrix.x4 (stride 36 uints -> conflict-free).
// ---------------------------------------------------------------------------
#define GSTG  4608                     // uints per tile stage (128*36)
#define GEMM_SMEM (6 * GSTG * 4)       // 110592 bytes

template<bool HALF_OUT>
__device__ __forceinline__ void gemm_body(
    const __half* __restrict__ A, const __half* __restrict__ W,
    const float* __restrict__ bias, void* Cv)
{
    extern __shared__ __align__(16) unsigned sm[];
    const int tid = threadIdx.x;
    const int warp = tid >> 5, lane = tid & 31;
    const int gid = lane >> 2, tig = lane & 3;
    const int wm = warp >> 2, wn = warp & 3;
    const int m0 = blockIdx.y * 128, n0 = blockIdx.x * 128;
    const uint32_t smb = smem_u32(sm);

    // ldmatrix lane-mapped offsets (in uints, relative to stage base)
    const int a_row = wm * 64 + (lane & 15);            // + ma*16
    const int a_col = (lane >> 4) * 4;                  // + s*8
    const int b_row = wn * 32 + ((lane & 16) >> 1) + (lane & 7);  // + nbp*16
    const int b_col = ((lane & 8) >> 1);                // + s*8

    float c[4][4][4] = {};

    auto issue = [&](int stage) {
        const int buf = stage % 3;
        const long k0 = (long)stage * 64;
        const uint32_t ab = smb + buf * (GSTG * 4);
        const uint32_t bb = smb + 3 * (GSTG * 4) + buf * (GSTG * 4);
        #pragma unroll
        for (int u = 0; u < 4; u++) {
            int chunk = tid + 256 * u;
            int row = chunk >> 3, qq = chunk & 7;
            cp16(ab + (row * 36 + qq * 4) * 4, &A[(long)(m0 + row) * 1024 + k0 + qq * 8]);
        }
        #pragma unroll
        for (int u = 0; u < 4; u++) {
            int chunk = tid + 256 * u;
            int row = chunk >> 3, qq = chunk & 7;
            cp16(bb + (row * 36 + qq * 4) * 4, &W[(long)(n0 + row) * 1024 + k0 + qq * 8]);
        }
        CP_COMMIT();
    };

    issue(0);
    issue(1);

    for (int ch = 0; ch < 16; ch++) {
        if (ch < 14) asm volatile("cp.async.wait_group 1;" ::: "memory");
        else         asm volatile("cp.async.wait_group 0;" ::: "memory");
        __syncthreads();
        if (ch + 2 < 16) issue(ch + 2);

        const uint32_t Ab = smb + (ch % 3) * (GSTG * 4);
        const uint32_t Bb = smb + (3 + ch % 3) * (GSTG * 4);
        #pragma unroll
        for (int s = 0; s < 4; s++) {
            unsigned a[4][4], b[4][2];
            #pragma unroll
            for (int ma = 0; ma < 4; ma++)
                ldm_x4(a[ma], Ab + ((a_row + ma * 16) * 36 + s * 8 + a_col) * 4);
            #pragma unroll
            for (int nbp = 0; nbp < 2; nbp++) {
                unsigned r[4];
                ldm_x4(r, Bb + ((b_row + nbp * 16) * 36 + s * 8 + b_col) * 4);
                b[2 * nbp][0] = r[0]; b[2 * nbp][1] = r[1];
                b[2 * nbp + 1][0] = r[2]; b[2 * nbp + 1][1] = r[3];
            }
            #pragma unroll
            for (int ma = 0; ma < 4; ma++)
                #pragma unroll
                for (int nb = 0; nb < 4; nb++)
                    mma_f16(c[ma][nb], a[ma], b[nb]);
        }
    }

    #pragma unroll
    for (int ma = 0; ma < 4; ma++) {
        int r = m0 + wm * 64 + ma * 16 + gid;
        #pragma unroll
        for (int nb = 0; nb < 4; nb++) {
            int col = n0 + wn * 32 + nb * 8 + 2 * tig;
            float b0 = bias[col], b1 = bias[col + 1];
            if (HALF_OUT) {
                __half* C = (__half*)Cv;
                __half2 v0 = __floats2half2_rn(c[ma][nb][0] + b0, c[ma][nb][1] + b1);
                __half2 v1 = __floats2half2_rn(c[ma][nb][2] + b0, c[ma][nb][3] + b1);
                *(__half2*)&C[(long)r * 1024 + col]       = v0;
                *(__half2*)&C[(long)(r + 8) * 1024 + col] = v1;
            } else {
                float* C = (float*)Cv;
                *(float2*)&C[(long)r * 1024 + col] =
                    make_float2(c[ma][nb][0] + b0, c[ma][nb][1] + b1);
                *(float2*)&C[(long)(r + 8) * 1024 + col] =
                    make_float2(c[ma][nb][2] + b0, c[ma][nb][3] + b1);
            }
        }
    }
}

__global__ __launch_bounds__(256, 2) void gemm_qkv(
    const float* __restrict__ bq, const float* __restrict__ bk, const float* __restrict__ bv)
{
    if (blockIdx.z == 0)      gemm_body<true>(g_xq, g_wq, bq, g_q);
    else if (blockIdx.z == 1) gemm_body<true>(g_xk, g_wk, bk, g_k);
    else                      gemm_body<true>(g_xv, g_wv, bv, g_v);
}

__global__ __launch_bounds__(256, 2) void gemm_out(
    const float* __restrict__ bo, float* __restrict__ C)
{
    gemm_body<false>(g_ao, g_wo, bo, C);
}

// ---------------------------------------------------------------------------
// Flash attention, all-fp16 mma, register-resident P, ldmatrix Q/K fragments.
// Block = 128 rows of one (n,h), BC=64 cols. Row r = ql*2+x, col c = kl*2+y.
// ---------------------------------------------------------------------------
#define ATTN_SMEM_BYTES ((64*36 + 32*68 + 128*36 + 64*36) * 4)

__global__ __launch_bounds__(256, 2) void attn_mma(const int* __restrict__ mask)
{
    extern __shared__ unsigned smA[];
    unsigned* Ks = smA;                   // half2 [c:64][36]
    unsigned* Vt = Ks + 64 * 36;          // half2 pairs-along-c [c2:32][68]
    unsigned* Qs = Vt + 32 * 68;          // half2 [row:128][36]
    int* msk = (int*)(Qs + 128 * 36);     // [ql:64][36]

    const int nh = blockIdx.y, n = nh >> 3, h = nh & 7;
    const int bx = blockIdx.x;
    const int tid = threadIdx.x;
    const int warp = tid >> 5, lane = tid & 31;
    const int gid = lane >> 2, tig = lane & 3;
    const int r0 = warp * 16 + gid, r1 = r0 + 8;
    const uint32_t ks_base = smem_u32(Ks);
    const uint32_t qs_base = smem_u32(Qs);

    // ldmatrix lane-mapped offsets
    const int lm_arow = (lane & 15), lm_acol = (lane >> 4) * 4;           // A-style
    const int lm_brow = ((lane & 16) >> 1) + (lane & 7), lm_bcol = ((lane & 8) >> 1); // B-style

    const __half2 sc2 = __floats2half2_rn(SCALE, SCALE);

    // Stage Q (pre-scaled, half2): 128 rows x 16 groups of 4 halves
    #pragma unroll
    for (int u = 0; u < 8; u++) {
        int idx = tid + 256 * u;
        int row = idx >> 4, d = (idx & 15) * 4;
        int rg = bx * 128 + row;
        int ql = rg >> 1, x = rg & 1;
        uint2 v = *(const uint2*)&g_q[(long)(n * SEQ + ql) * DQ + x * 512 + h * 64 + d];
        __half2 h0 = __hmul2(*(__half2*)&v.x, sc2);
        __half2 h1 = __hmul2(*(__half2*)&v.y, sc2);
        Qs[row * 36 + d / 2]     = *(unsigned*)&h0;
        Qs[row * 36 + d / 2 + 1] = *(unsigned*)&h1;
    }
    __syncthreads();
    unsigned q[4][4];
    #pragma unroll
    for (int s = 0; s < 4; s++)
        ldm_x4(q[s], qs_base + ((warp * 16 + lm_arow) * 36 + s * 8 + lm_acol) * 4);
    __syncthreads();

    float o[8][4] = {};
    float m0 = -INFINITY, m1 = -INFINITY, l0 = 0.f, l1 = 0.f;
    const int qll0 = r0 >> 1, qll1 = qll0 + 4;

    for (int t = 0; t < 16; t++) {
        // K tile: 64 cols x 64 dims (half2, direct)
        #pragma unroll
        for (int u = 0; u < 4; u++) {
            int idx = tid + 256 * u;
            int cc = idx >> 4, d = (idx & 15) * 4;
            int cg = t * 64 + cc;
            int kl = cg >> 1, y = cg & 1;
            uint2 kv = *(const uint2*)&g_k[(long)(n * SEQ + kl) * DQ + y * 512 + h * 64 + d];
            *(uint2*)&Ks[cc * 36 + d / 2] = kv;
        }
        // V tile repacked: Vt[c2][d] = half2{ V[2*c2][d], V[2*c2+1][d] }
        #pragma unroll
        for (int u = 0; u < 2; u++) {
            int idx = tid + 256 * u;
            int c2 = idx >> 4, d4 = (idx & 15) * 4;
            int kl = t * 32 + c2;
            long base = (long)(n * SEQ + kl) * DQ + h * 64 + d4;
            uint2 lo = *(const uint2*)&g_v[base];          // y=0 (even c)
            uint2 hi = *(const uint2*)&g_v[base + 512];    // y=1 (odd c)
            __half2 l0h = *(__half2*)&lo.x, l1h = *(__half2*)&lo.y;
            __half2 h0h = *(__half2*)&hi.x, h1h = *(__half2*)&hi.y;
            __half2 p0 = __halves2half2(__low2half(l0h),  __low2half(h0h));
            __half2 p1 = __halves2half2(__high2half(l0h), __high2half(h0h));
            __half2 p2 = __halves2half2(__low2half(l1h),  __low2half(h1h));
            __half2 p3 = __halves2half2(__high2half(l1h), __high2half(h1h));
            *(uint4*)&Vt[c2 * 68 + d4] = make_uint4(
                *(unsigned*)&p0, *(unsigned*)&p1, *(unsigned*)&p2, *(unsigned*)&p3);
        }
        // mask tile: 64 ql x 32 kl
        #pragma unroll
        for (int u = 0; u < 8; u++) {
            int idx = tid + 256 * u;
            int qlr = idx >> 5, klr = idx & 31;
            msk[qlr * 36 + klr] = mask[(long)(n * SEQ + bx * 64 + qlr) * SEQ + t * 32 + klr];
        }
        __syncthreads();

        // S(128x64) = Q K^T  (fp16, 4 k16-steps, K frags via ldmatrix)
        float s[8][4] = {};
        #pragma unroll
        for (int ks = 0; ks < 4; ks++) {
            unsigned bb[8][2];
            #pragma unroll
            for (int jp = 0; jp < 4; jp++) {
                unsigned r[4];
                ldm_x4(r, ks_base + ((jp * 16 + lm_brow) * 36 + ks * 8 + lm_bcol) * 4);
                bb[2 * jp][0] = r[0]; bb[2 * jp][1] = r[1];
                bb[2 * jp + 1][0] = r[2]; bb[2 * jp + 1][1] = r[3];
            }
            #pragma unroll
            for (int j = 0; j < 8; j++)
                mma_f16(s[j], q[ks], bb[j]);
        }

        // Mask + online softmax (rows r0, r1 per thread)
        float mx0 = m0, mx1 = m1;
        #pragma unroll
        for (int j = 0; j < 8; j++) {
            int klc = 4 * j + tig;
            bool k0m = msk[qll0 * 36 + klc] != 0;
            bool k1m = msk[qll1 * 36 + klc] != 0;
            s[j][0] = k0m ? s[j][0] : NEG;
            s[j][1] = k0m ? s[j][1] : NEG;
            s[j][2] = k1m ? s[j][2] : NEG;
            s[j][3] = k1m ? s[j][3] : NEG;
            mx0 = fmaxf(mx0, fmaxf(s[j][0], s[j][1]));
            mx1 = fmaxf(mx1, fmaxf(s[j][2], s[j][3]));
        }
        mx0 = fmaxf(mx0, __shfl_xor_sync(0xffffffffu, mx0, 1));
        mx0 = fmaxf(mx0, __shfl_xor_sync(0xffffffffu, mx0, 2));
        mx1 = fmaxf(mx1, __shfl_xor_sync(0xffffffffu, mx1, 1));
        mx1 = fmaxf(mx1, __shfl_xor_sync(0xffffffffu, mx1, 2));
        float a0 = __expf(m0 - mx0), a1 = __expf(m1 - mx1);
        float sum0 = 0.f, sum1 = 0.f;
        #pragma unroll
        for (int j = 0; j < 8; j++) {
            s[j][0] = __expf(s[j][0] - mx0);
            s[j][1] = __expf(s[j][1] - mx0);
            s[j][2] = __expf(s[j][2] - mx1);
            s[j][3] = __expf(s[j][3] - mx1);
            sum0 += s[j][0] + s[j][1];
            sum1 += s[j][2] + s[j][3];
        }
        sum0 += __shfl_xor_sync(0xffffffffu, sum0, 1);
        sum0 += __shfl_xor_sync(0xffffffffu, sum0, 2);
        sum1 += __shfl_xor_sync(0xffffffffu, sum1, 1);
        sum1 += __shfl_xor_sync(0xffffffffu, sum1, 2);
        l0 = l0 * a0 + sum0; l1 = l1 * a1 + sum1;
        m0 = mx0; m1 = mx1;
        #pragma unroll
        for (int j = 0; j < 8; j++) {
            o[j][0] *= a0; o[j][1] *= a0; o[j][2] *= a1; o[j][3] *= a1;
        }

        // O += P V (fp16, P fragments built in registers)
        #pragma unroll
        for (int ks = 0; ks < 4; ks++) {
            unsigned a[4];
            a[0] = pack_h2(s[2 * ks][0],     s[2 * ks][1]);
            a[1] = pack_h2(s[2 * ks][2],     s[2 * ks][3]);
            a[2] = pack_h2(s[2 * ks + 1][0], s[2 * ks + 1][1]);
            a[3] = pack_h2(s[2 * ks + 1][2], s[2 * ks + 1][3]);
            #pragma unroll
            for (int j = 0; j < 8; j++) {
                unsigned b[2];
                b[0] = Vt[(8 * ks + tig) * 68 + 8 * j + gid];
                b[1] = Vt[(8 * ks + tig + 4) * 68 + 8 * j + gid];
                mma_f16(o[j], a, b);
            }
        }
        __syncthreads();
    }

    // Normalize + store (half, consumed by gemm_out)
    float inv0 = 1.f / l0, inv1 = 1.f / l1;
    int rg0 = bx * 128 + r0, rg1 = rg0 + 8;
    int ql0 = rg0 >> 1, x0 = rg0 & 1;
    int ql1 = rg1 >> 1, x1 = rg1 & 1;
    __half* out0 = &g_ao[(long)(n * SEQ + ql0) * DQ + x0 * 512 + h * 64];
    __half* out1 = &g_ao[(long)(n * SEQ + ql1) * DQ + x1 * 512 + h * 64];
    #pragma unroll
    for (int j = 0; j < 8; j++) {
        *(__half2*)&out0[8 * j + 2 * tig] = __floats2half2_rn(o[j][0] * inv0, o[j][1] * inv0);
        *(__half2*)&out1[8 * j + 2 * tig] = __floats2half2_rn(o[j][2] * inv1, o[j][3] * inv1);
    }
}

// ---------------------------------------------------------------------------
extern "C" void kernel_launch(void* const* d_in, const int* in_sizes, int n_in,
                              void* d_out, int out_size)
{
    const float* query = (const float*)d_in[0];
    const float* key   = (const float*)d_in[1];
    const float* value = (const float*)d_in[2];
    const int*   mask  = (const int*)  d_in[3];
    const float* Wv    = (const float*)d_in[4];
    const float* bv    = (const float*)d_in[5];
    const float* Wk    = (const float*)d_in[6];
    const float* bk    = (const float*)d_in[7];
    const float* Wq    = (const float*)d_in[8];
    const float* bq    = (const float*)d_in[9];
    const float* Wo    = (const float*)d_in[10];
    const float* bo    = (const float*)d_in[11];
    float* out = (float*)d_out;

    static bool attr_set = false;
    if (!attr_set) {
        cudaFuncSetAttribute(attn_mma, cudaFuncAttributeMaxDynamicSharedMemorySize,
                             ATTN_SMEM_BYTES);
        cudaFuncSetAttribute(gemm_qkv, cudaFuncAttributeMaxDynamicSharedMemorySize,
                             GEMM_SMEM);
        cudaFuncSetAttribute(gemm_out, cudaFuncAttributeMaxDynamicSharedMemorySize,
                             GEMM_SMEM);
        attr_set = true;
    }

    dim3 bb(256);
    cvt_kernel<<<2048, bb>>>(query, key, value, Wv, Wk, Wq, Wo);
    gemm_qkv<<<dim3(8, 32, 3), bb, GEMM_SMEM>>>(bq, bk, bv);
    attn_mma<<<dim3(8, 64), bb, ATTN_SMEM_BYTES>>>(mask);
    gemm_out<<<dim3(8, 32), bb, GEMM_SMEM>>>(bo, out);
}

// round 8
// speedup vs baseline: 1.1195x; 1.1195x over previous
#include <cuda_runtime.h>
#include <cuda_fp16.h>
#include <math.h>
#include <cstdint>

#define SEQ    512
#define DQ     1024
#define MTOK   4096
#define SCALE  0.044194173824159216f   // 1/sqrt(512)
#define NEG    -4.4194174e18f          // -1e20 * SCALE

// Scratch (device globals; no allocation allowed)
__device__ __half g_xq[MTOK * DQ];   // converted inputs
__device__ __half g_xk[MTOK * DQ];
__device__ __half g_xv[MTOK * DQ];
__device__ __half g_wq[DQ * DQ];     // converted weights
__device__ __half g_wk[DQ * DQ];
__device__ __half g_wv[DQ * DQ];
__device__ __half g_wo[DQ * DQ];
__device__ __half g_q [MTOK * DQ];   // projections
__device__ __half g_k [MTOK * DQ];
__device__ __half g_v [MTOK * DQ];
__device__ __half g_ao[MTOK * DQ];   // attention output

// ---------------------------------------------------------------------------
// helpers
// ---------------------------------------------------------------------------
__device__ __forceinline__ void mma_f16(float* c, const unsigned* a, const unsigned* b) {
    asm volatile(
        "mma.sync.aligned.m16n8k16.row.col.f32.f16.f16.f32 "
        "{%0,%1,%2,%3}, {%4,%5,%6,%7}, {%8,%9}, {%0,%1,%2,%3};\n"
        : "+f"(c[0]), "+f"(c[1]), "+f"(c[2]), "+f"(c[3])
        : "r"(a[0]), "r"(a[1]), "r"(a[2]), "r"(a[3]), "r"(b[0]), "r"(b[1]));
}
__device__ __forceinline__ uint32_t smem_u32(const void* p) {
    uint32_t a;
    asm("{ .reg .u64 t; cvta.to.shared.u64 t, %1; cvt.u32.u64 %0, t; }" : "=r"(a) : "l"(p));
    return a;
}
__device__ __forceinline__ void cp16(uint32_t s, const void* g) {
    asm volatile("cp.async.cg.shared.global [%0], [%1], 16;" :: "r"(s), "l"(g));
}
#define CP_COMMIT() asm volatile("cp.async.commit_group;" ::: "memory")
__device__ __forceinline__ unsigned pack_h2(float x, float y) {
    __half2 h = __floats2half2_rn(x, y);
    return *(unsigned*)&h;
}

// ---------------------------------------------------------------------------
// f32 -> f16 conversion of inputs and weights, one pass.
// ---------------------------------------------------------------------------
__global__ __launch_bounds__(256) void cvt_kernel(
    const float* __restrict__ q, const float* __restrict__ k, const float* __restrict__ v,
    const float* __restrict__ wv, const float* __restrict__ wk,
    const float* __restrict__ wq, const float* __restrict__ wo)
{
    const long stride = (long)gridDim.x * blockDim.x;
    for (long i = (long)blockIdx.x * blockDim.x + threadIdx.x; i < 4194304; i += stride) {
        const float* src; __half* dst; long off;
        if (i < 3145728) {
            int which = (int)(i >> 20);
            off = i & 1048575;
            src = which == 0 ? q : which == 1 ? k : v;
            dst = which == 0 ? g_xq : which == 1 ? g_xk : g_xv;
        } else {
            long j = i - 3145728;
            int which = (int)(j >> 18);
            off = j & 262143;
            src = which == 0 ? wv : which == 1 ? wk : which == 2 ? wq : wo;
            dst = which == 0 ? g_wv : which == 1 ? g_wk : which == 2 ? g_wq : g_wo;
        }
        float4 val = ((const float4*)src)[off];
        uint2 h;
        h.x = pack_h2(val.x, val.y);
        h.y = pack_h2(val.z, val.w);
        ((uint2*)dst)[off] = h;
    }
}

// ---------------------------------------------------------------------------
// Pipelined fp16 GEMM: C[4096][1024] = A @ W^T + bias.
// 128x128 block tile, BK=64, 3-stage cp.async ring.
// 512 threads / 16 warps (4x4), warp tile 32x32 -> 32 accum regs/thread,
// fits 64-reg budget for 2 CTAs x 512 threads (8 warps/SMSP).
// ---------------------------------------------------------------------------
#define GSTG  4608                     // uints per tile stage (128*36)
#define GEMM_SMEM (6 * GSTG * 4)       // 110592 bytes

template<bool HALF_OUT>
__device__ __forceinline__ void gemm_body(
    const __half* __restrict__ A, const __half* __restrict__ W,
    const float* __restrict__ bias, void* Cv)
{
    extern __shared__ __align__(16) unsigned sm[];
    const int tid = threadIdx.x;
    const int warp = tid >> 5, lane = tid & 31;
    const int gid = lane >> 2, tig = lane & 3;
    const int wm = warp >> 2, wn = warp & 3;     // 4x4 warp grid
    const int m0 = blockIdx.y * 128, n0 = blockIdx.x * 128;
    const uint32_t smb = smem_u32(sm);

    float c[2][4][4] = {};

    auto issue = [&](int stage) {
        const int buf = stage % 3;
        const long k0 = (long)stage * 64;
        const uint32_t ab = smb + buf * (GSTG * 4);
        const uint32_t bb = smb + 3 * (GSTG * 4) + buf * (GSTG * 4);
        #pragma unroll
        for (int u = 0; u < 2; u++) {
            int chunk = tid + 512 * u;
            int row = chunk >> 3, qq = chunk & 7;
            cp16(ab + (row * 36 + qq * 4) * 4, &A[(long)(m0 + row) * 1024 + k0 + qq * 8]);
        }
        #pragma unroll
        for (int u = 0; u < 2; u++) {
            int chunk = tid + 512 * u;
            int row = chunk >> 3, qq = chunk & 7;
            cp16(bb + (row * 36 + qq * 4) * 4, &W[(long)(n0 + row) * 1024 + k0 + qq * 8]);
        }
        CP_COMMIT();
    };

    issue(0);
    issue(1);

    for (int ch = 0; ch < 16; ch++) {
        if (ch < 14) asm volatile("cp.async.wait_group 1;" ::: "memory");
        else         asm volatile("cp.async.wait_group 0;" ::: "memory");
        __syncthreads();
        if (ch + 2 < 16) issue(ch + 2);

        unsigned* Ab = sm + (ch % 3) * GSTG;
        unsigned* Bb = sm + 3 * GSTG + (ch % 3) * GSTG;
        #pragma unroll
        for (int s = 0; s < 4; s++) {
            const int k2 = s * 8;
            unsigned a[2][4], b[4][2];
            #pragma unroll
            for (int ma = 0; ma < 2; ma++) {
                int r = wm * 32 + ma * 16 + gid;
                a[ma][0] = Ab[r * 36 + k2 + tig];
                a[ma][1] = Ab[(r + 8) * 36 + k2 + tig];
                a[ma][2] = Ab[r * 36 + k2 + tig + 4];
                a[ma][3] = Ab[(r + 8) * 36 + k2 + tig + 4];
            }
            #pragma unroll
            for (int nb = 0; nb < 4; nb++) {
                int cc = wn * 32 + nb * 8 + gid;
                b[nb][0] = Bb[cc * 36 + k2 + tig];
                b[nb][1] = Bb[cc * 36 + k2 + tig + 4];
            }
            #pragma unroll
            for (int ma = 0; ma < 2; ma++)
                #pragma unroll
                for (int nb = 0; nb < 4; nb++)
                    mma_f16(c[ma][nb], a[ma], b[nb]);
        }
    }

    #pragma unroll
    for (int ma = 0; ma < 2; ma++) {
        int r = m0 + wm * 32 + ma * 16 + gid;
        #pragma unroll
        for (int nb = 0; nb < 4; nb++) {
            int col = n0 + wn * 32 + nb * 8 + 2 * tig;
            float b0 = bias[col], b1 = bias[col + 1];
            if (HALF_OUT) {
                __half* C = (__half*)Cv;
                __half2 v0 = __floats2half2_rn(c[ma][nb][0] + b0, c[ma][nb][1] + b1);
                __half2 v1 = __floats2half2_rn(c[ma][nb][2] + b0, c[ma][nb][3] + b1);
                *(__half2*)&C[(long)r * 1024 + col]       = v0;
                *(__half2*)&C[(long)(r + 8) * 1024 + col] = v1;
            } else {
                float* C = (float*)Cv;
                *(float2*)&C[(long)r * 1024 + col] =
                    make_float2(c[ma][nb][0] + b0, c[ma][nb][1] + b1);
                *(float2*)&C[(long)(r + 8) * 1024 + col] =
                    make_float2(c[ma][nb][2] + b0, c[ma][nb][3] + b1);
            }
        }
    }
}

__global__ __launch_bounds__(512, 2) void gemm_qkv(
    const float* __restrict__ bq, const float* __restrict__ bk, const float* __restrict__ bv)
{
    if (blockIdx.z == 0)      gemm_body<true>(g_xq, g_wq, bq, g_q);
    else if (blockIdx.z == 1) gemm_body<true>(g_xk, g_wk, bk, g_k);
    else                      gemm_body<true>(g_xv, g_wv, bv, g_v);
}

__global__ __launch_bounds__(512, 2) void gemm_out(
    const float* __restrict__ bo, float* __restrict__ C)
{
    gemm_body<false>(g_ao, g_wo, bo, C);
}

// ---------------------------------------------------------------------------
// Flash attention, all-fp16 mma, register-resident P (exact R6 form).
// Block = 128 rows of one (n,h), BC=64 cols. Row r = ql*2+x, col c = kl*2+y.
// ---------------------------------------------------------------------------
#define ATTN_SMEM_BYTES ((64*36 + 32*68 + 128*36 + 64*36) * 4)

__global__ __launch_bounds__(256, 2) void attn_mma(const int* __restrict__ mask)
{
    extern __shared__ unsigned smA[];
    unsigned* Ks = smA;                   // half2 [c:64][36]
    unsigned* Vt = Ks + 64 * 36;          // half2 pairs-along-c [c2:32][68]
    unsigned* Qs = Vt + 32 * 68;          // half2 [row:128][36]
    int* msk = (int*)(Qs + 128 * 36);     // [ql:64][36]

    const int nh = blockIdx.y, n = nh >> 3, h = nh & 7;
    const int bx = blockIdx.x;
    const int tid = threadIdx.x;
    const int warp = tid >> 5, lane = tid & 31;
    const int gid = lane >> 2, tig = lane & 3;
    const int r0 = warp * 16 + gid, r1 = r0 + 8;

    const __half2 sc2 = __floats2half2_rn(SCALE, SCALE);

    // Stage Q (pre-scaled, half2): 128 rows x 16 groups of 4 halves
    #pragma unroll
    for (int u = 0; u < 8; u++) {
        int idx = tid + 256 * u;
        int row = idx >> 4, d = (idx & 15) * 4;
        int rg = bx * 128 + row;
        int ql = rg >> 1, x = rg & 1;
        uint2 v = *(const uint2*)&g_q[(long)(n * SEQ + ql) * DQ + x * 512 + h * 64 + d];
        __half2 h0 = __hmul2(*(__half2*)&v.x, sc2);
        __half2 h1 = __hmul2(*(__half2*)&v.y, sc2);
        Qs[row * 36 + d / 2]     = *(unsigned*)&h0;
        Qs[row * 36 + d / 2 + 1] = *(unsigned*)&h1;
    }
    __syncthreads();
    unsigned q[4][4];
    #pragma unroll
    for (int s = 0; s < 4; s++) {
        q[s][0] = Qs[r0 * 36 + 8 * s + tig];
        q[s][1] = Qs[r1 * 36 + 8 * s + tig];
        q[s][2] = Qs[r0 * 36 + 8 * s + tig + 4];
        q[s][3] = Qs[r1 * 36 + 8 * s + tig + 4];
    }
    __syncthreads();

    float o[8][4] = {};
    float m0 = -INFINITY, m1 = -INFINITY, l0 = 0.f, l1 = 0.f;
    const int qll0 = r0 >> 1, qll1 = qll0 + 4;

    for (int t = 0; t < 16; t++) {
        // K tile: 64 cols x 64 dims (half2, direct)
        #pragma unroll
        for (int u = 0; u < 4; u++) {
            int idx = tid + 256 * u;
            int cc = idx >> 4, d = (idx & 15) * 4;
            int cg = t * 64 + cc;
            int kl = cg >> 1, y = cg & 1;
            uint2 kv = *(const uint2*)&g_k[(long)(n * SEQ + kl) * DQ + y * 512 + h * 64 + d];
            *(uint2*)&Ks[cc * 36 + d / 2] = kv;
        }
        // V tile repacked: Vt[c2][d] = half2{ V[2*c2][d], V[2*c2+1][d] }
        #pragma unroll
        for (int u = 0; u < 2; u++) {
            int idx = tid + 256 * u;
            int c2 = idx >> 4, d4 = (idx & 15) * 4;
            int kl = t * 32 + c2;
            long base = (long)(n * SEQ + kl) * DQ + h * 64 + d4;
            uint2 lo = *(const uint2*)&g_v[base];          // y=0 (even c)
            uint2 hi = *(const uint2*)&g_v[base + 512];    // y=1 (odd c)
            __half2 l0h = *(__half2*)&lo.x, l1h = *(__half2*)&lo.y;
            __half2 h0h = *(__half2*)&hi.x, h1h = *(__half2*)&hi.y;
            __half2 p0 = __halves2half2(__low2half(l0h),  __low2half(h0h));
            __half2 p1 = __halves2half2(__high2half(l0h), __high2half(h0h));
            __half2 p2 = __halves2half2(__low2half(l1h),  __low2half(h1h));
            __half2 p3 = __halves2half2(__high2half(l1h), __high2half(h1h));
            *(uint4*)&Vt[c2 * 68 + d4] = make_uint4(
                *(unsigned*)&p0, *(unsigned*)&p1, *(unsigned*)&p2, *(unsigned*)&p3);
        }
        // mask tile: 64 ql x 32 kl
        #pragma unroll
        for (int u = 0; u < 8; u++) {
            int idx = tid + 256 * u;
            int qlr = idx >> 5, klr = idx & 31;
            msk[qlr * 36 + klr] = mask[(long)(n * SEQ + bx * 64 + qlr) * SEQ + t * 32 + klr];
        }
        __syncthreads();

        // S(128x64) = Q K^T  (fp16, 4 k16-steps)
        float s[8][4] = {};
        #pragma unroll
        for (int ks = 0; ks < 4; ks++) {
            #pragma unroll
            for (int j = 0; j < 8; j++) {
                unsigned b[2];
                b[0] = Ks[(8 * j + gid) * 36 + 8 * ks + tig];
                b[1] = Ks[(8 * j + gid) * 36 + 8 * ks + tig + 4];
                mma_f16(s[j], q[ks], b);
            }
        }

        // Mask + online softmax (rows r0, r1 per thread)
        float mx0 = m0, mx1 = m1;
        #pragma unroll
        for (int j = 0; j < 8; j++) {
            int klc = 4 * j + tig;
            bool k0m = msk[qll0 * 36 + klc] != 0;
            bool k1m = msk[qll1 * 36 + klc] != 0;
            s[j][0] = k0m ? s[j][0] : NEG;
            s[j][1] = k0m ? s[j][1] : NEG;
            s[j][2] = k1m ? s[j][2] : NEG;
            s[j][3] = k1m ? s[j][3] : NEG;
            mx0 = fmaxf(mx0, fmaxf(s[j][0], s[j][1]));
            mx1 = fmaxf(mx1, fmaxf(s[j][2], s[j][3]));
        }
        mx0 = fmaxf(mx0, __shfl_xor_sync(0xffffffffu, mx0, 1));
        mx0 = fmaxf(mx0, __shfl_xor_sync(0xffffffffu, mx0, 2));
        mx1 = fmaxf(mx1, __shfl_xor_sync(0xffffffffu, mx1, 1));
        mx1 = fmaxf(mx1, __shfl_xor_sync(0xffffffffu, mx1, 2));
        float a0 = __expf(m0 - mx0), a1 = __expf(m1 - mx1);
        float sum0 = 0.f, sum1 = 0.f;
        #pragma unroll
        for (int j = 0; j < 8; j++) {
            s[j][0] = __expf(s[j][0] - mx0);
            s[j][1] = __expf(s[j][1] - mx0);
            s[j][2] = __expf(s[j][2] - mx1);
            s[j][3] = __expf(s[j][3] - mx1);
            sum0 += s[j][0] + s[j][1];
            sum1 += s[j][2] + s[j][3];
        }
        sum0 += __shfl_xor_sync(0xffffffffu, sum0, 1);
        sum0 += __shfl_xor_sync(0xffffffffu, sum0, 2);
        sum1 += __shfl_xor_sync(0xffffffffu, sum1, 1);
        sum1 += __shfl_xor_sync(0xffffffffu, sum1, 2);
        l0 = l0 * a0 + sum0; l1 = l1 * a1 + sum1;
        m0 = mx0; m1 = mx1;
        #pragma unroll
        for (int j = 0; j < 8; j++) {
            o[j][0] *= a0; o[j][1] *= a0; o[j][2] *= a1; o[j][3] *= a1;
        }

        // O += P V (fp16, P fragments built in registers)
        #pragma unroll
        for (int ks = 0; ks < 4; ks++) {
            unsigned a[4];
            a[0] = pack_h2(s[2 * ks][0],     s[2 * ks][1]);
            a[1] = pack_h2(s[2 * ks][2],     s[2 * ks][3]);
            a[2] = pack_h2(s[2 * ks + 1][0], s[2 * ks + 1][1]);
            a[3] = pack_h2(s[2 * ks + 1][2], s[2 * ks + 1][3]);
            #pragma unroll
            for (int j = 0; j < 8; j++) {
                unsigned b[2];
                b[0] = Vt[(8 * ks + tig) * 68 + 8 * j + gid];
                b[1] = Vt[(8 * ks + tig + 4) * 68 + 8 * j + gid];
                mma_f16(o[j], a, b);
            }
        }
        __syncthreads();
    }

    // Normalize + store (half, consumed by gemm_out)
    float inv0 = 1.f / l0, inv1 = 1.f / l1;
    int rg0 = bx * 128 + r0, rg1 = rg0 + 8;
    int ql0 = rg0 >> 1, x0 = rg0 & 1;
    int ql1 = rg1 >> 1, x1 = rg1 & 1;
    __half* out0 = &g_ao[(long)(n * SEQ + ql0) * DQ + x0 * 512 + h * 64];
    __half* out1 = &g_ao[(long)(n * SEQ + ql1) * DQ + x1 * 512 + h * 64];
    #pragma unroll
    for (int j = 0; j < 8; j++) {
        *(__half2*)&out0[8 * j + 2 * tig] = __floats2half2_rn(o[j][0] * inv0, o[j][1] * inv0);
        *(__half2*)&out1[8 * j + 2 * tig] = __floats2half2_rn(o[j][2] * inv1, o[j][3] * inv1);
    }
}

// ---------------------------------------------------------------------------
extern "C" void kernel_launch(void* const* d_in, const int* in_sizes, int n_in,
                              void* d_out, int out_size)
{
    const float* query = (const float*)d_in[0];
    const float* key   = (const float*)d_in[1];
    const float* value = (const float*)d_in[2];
    const int*   mask  = (const int*)  d_in[3];
    const float* Wv    = (const float*)d_in[4];
    const float* bv    = (const float*)d_in[5];
    const float* Wk    = (const float*)d_in[6];
    const float* bk    = (const float*)d_in[7];
    const float* Wq    = (const float*)d_in[8];
    const float* bq    = (const float*)d_in[9];
    const float* Wo    = (const float*)d_in[10];
    const float* bo    = (const float*)d_in[11];
    float* out = (float*)d_out;

    static bool attr_set = false;
    if (!attr_set) {
        cudaFuncSetAttribute(attn_mma, cudaFuncAttributeMaxDynamicSharedMemorySize,
                             ATTN_SMEM_BYTES);
        cudaFuncSetAttribute(gemm_qkv, cudaFuncAttributeMaxDynamicSharedMemorySize,
                             GEMM_SMEM);
        cudaFuncSetAttribute(gemm_out, cudaFuncAttributeMaxDynamicSharedMemorySize,
                             GEMM_SMEM);
        attr_set = true;
    }

    cvt_kernel<<<2048, 256>>>(query, key, value, Wv, Wk, Wq, Wo);
    gemm_qkv<<<dim3(8, 32, 3), 512, GEMM_SMEM>>>(bq, bk, bv);
    attn_mma<<<dim3(8, 64), 256, ATTN_SMEM_BYTES>>>(mask);
    gemm_out<<<dim3(8, 32), 512, GEMM_SMEM>>>(bo, out);
}

// round 9
// speedup vs baseline: 1.2884x; 1.1508x over previous
#include <cuda_runtime.h>
#include <cuda_fp16.h>
#include <math.h>
#include <cstdint>

#define SEQ    512
#define DQ     1024
#define MTOK   4096
#define SCALE  0.044194173824159216f   // 1/sqrt(512)
#define NEG    -4.4194174e18f          // -1e20 * SCALE

// Scratch (device globals; no allocation allowed)
__device__ __half g_xq[MTOK * DQ];   // converted inputs
__device__ __half g_xk[MTOK * DQ];
__device__ __half g_xv[MTOK * DQ];
__device__ __half g_wq[DQ * DQ];     // converted weights
__device__ __half g_wk[DQ * DQ];
__device__ __half g_wv[DQ * DQ];
__device__ __half g_wo[DQ * DQ];
__device__ __half g_q [MTOK * DQ];   // projections
__device__ __half g_k [MTOK * DQ];
__device__ __half g_v [MTOK * DQ];
__device__ __half g_ao[MTOK * DQ];   // attention output

// ---------------------------------------------------------------------------
// helpers
// ---------------------------------------------------------------------------
__device__ __forceinline__ void mma_f16(float* c, const unsigned* a, const unsigned* b) {
    asm volatile(
        "mma.sync.aligned.m16n8k16.row.col.f32.f16.f16.f32 "
        "{%0,%1,%2,%3}, {%4,%5,%6,%7}, {%8,%9}, {%0,%1,%2,%3};\n"
        : "+f"(c[0]), "+f"(c[1]), "+f"(c[2]), "+f"(c[3])
        : "r"(a[0]), "r"(a[1]), "r"(a[2]), "r"(a[3]), "r"(b[0]), "r"(b[1]));
}
__device__ __forceinline__ uint32_t smem_u32(const void* p) {
    uint32_t a;
    asm("{ .reg .u64 t; cvta.to.shared.u64 t, %1; cvt.u32.u64 %0, t; }" : "=r"(a) : "l"(p));
    return a;
}
__device__ __forceinline__ void cp16(uint32_t s, const void* g) {
    asm volatile("cp.async.cg.shared.global [%0], [%1], 16;" :: "r"(s), "l"(g));
}
#define CP_COMMIT() asm volatile("cp.async.commit_group;" ::: "memory")
#define CP_WAIT0()  asm volatile("cp.async.wait_group 0;" ::: "memory")
__device__ __forceinline__ unsigned pack_h2(float x, float y) {
    __half2 h = __floats2half2_rn(x, y);
    return *(unsigned*)&h;
}

// ---------------------------------------------------------------------------
// f32 -> f16 conversion of inputs and weights, one pass.
// ---------------------------------------------------------------------------
__global__ __launch_bounds__(256) void cvt_kernel(
    const float* __restrict__ q, const float* __restrict__ k, const float* __restrict__ v,
    const float* __restrict__ wv, const float* __restrict__ wk,
    const float* __restrict__ wq, const float* __restrict__ wo)
{
    const long stride = (long)gridDim.x * blockDim.x;
    for (long i = (long)blockIdx.x * blockDim.x + threadIdx.x; i < 4194304; i += stride) {
        const float* src; __half* dst; long off;
        if (i < 3145728) {
            int which = (int)(i >> 20);
            off = i & 1048575;
            src = which == 0 ? q : which == 1 ? k : v;
            dst = which == 0 ? g_xq : which == 1 ? g_xk : g_xv;
        } else {
            long j = i - 3145728;
            int which = (int)(j >> 18);
            off = j & 262143;
            src = which == 0 ? wv : which == 1 ? wk : which == 2 ? wq : wo;
            dst = which == 0 ? g_wv : which == 1 ? g_wk : which == 2 ? g_wq : g_wo;
        }
        float4 val = ((const float4*)src)[off];
        uint2 h;
        h.x = pack_h2(val.x, val.y);
        h.y = pack_h2(val.z, val.w);
        ((uint2*)dst)[off] = h;
    }
}

// ---------------------------------------------------------------------------
// Pipelined fp16 GEMM (exact R6 config): C = A @ W^T + bias.
// 128x128 tile, BK=64, 3-stage cp.async ring, 256 thr / 8 warps (2x4),
// warp tile 64x32, stride-36 conflict-free fragments.
// ---------------------------------------------------------------------------
#define GSTG  4608                     // uints per tile stage (128*36)
#define GEMM_SMEM (6 * GSTG * 4)       // 110592 bytes

template<bool HALF_OUT>
__device__ __forceinline__ void gemm_body(
    const __half* __restrict__ A, const __half* __restrict__ W,
    const float* __restrict__ bias, void* Cv)
{
    extern __shared__ __align__(16) unsigned sm[];
    const int tid = threadIdx.x;
    const int warp = tid >> 5, lane = tid & 31;
    const int gid = lane >> 2, tig = lane & 3;
    const int wm = warp >> 2, wn = warp & 3;
    const int m0 = blockIdx.y * 128, n0 = blockIdx.x * 128;
    const uint32_t smb = smem_u32(sm);

    float c[4][4][4] = {};

    auto issue = [&](int stage) {
        const int buf = stage % 3;
        const long k0 = (long)stage * 64;
        const uint32_t ab = smb + buf * (GSTG * 4);
        const uint32_t bb = smb + 3 * (GSTG * 4) + buf * (GSTG * 4);
        #pragma unroll
        for (int u = 0; u < 4; u++) {
            int chunk = tid + 256 * u;
            int row = chunk >> 3, qq = chunk & 7;
            cp16(ab + (row * 36 + qq * 4) * 4, &A[(long)(m0 + row) * 1024 + k0 + qq * 8]);
        }
        #pragma unroll
        for (int u = 0; u < 4; u++) {
            int chunk = tid + 256 * u;
            int row = chunk >> 3, qq = chunk & 7;
            cp16(bb + (row * 36 + qq * 4) * 4, &W[(long)(n0 + row) * 1024 + k0 + qq * 8]);
        }
        CP_COMMIT();
    };

    issue(0);
    issue(1);

    for (int ch = 0; ch < 16; ch++) {
        if (ch < 14) asm volatile("cp.async.wait_group 1;" ::: "memory");
        else         asm volatile("cp.async.wait_group 0;" ::: "memory");
        __syncthreads();
        if (ch + 2 < 16) issue(ch + 2);

        unsigned* Ab = sm + (ch % 3) * GSTG;
        unsigned* Bb = sm + 3 * GSTG + (ch % 3) * GSTG;
        #pragma unroll
        for (int s = 0; s < 4; s++) {
            const int k2 = s * 8;
            unsigned a[4][4], b[4][2];
            #pragma unroll
            for (int ma = 0; ma < 4; ma++) {
                int r = wm * 64 + ma * 16 + gid;
                a[ma][0] = Ab[r * 36 + k2 + tig];
                a[ma][1] = Ab[(r + 8) * 36 + k2 + tig];
                a[ma][2] = Ab[r * 36 + k2 + tig + 4];
                a[ma][3] = Ab[(r + 8) * 36 + k2 + tig + 4];
            }
            #pragma unroll
            for (int nb = 0; nb < 4; nb++) {
                int cc = wn * 32 + nb * 8 + gid;
                b[nb][0] = Bb[cc * 36 + k2 + tig];
                b[nb][1] = Bb[cc * 36 + k2 + tig + 4];
            }
            #pragma unroll
            for (int ma = 0; ma < 4; ma++)
                #pragma unroll
                for (int nb = 0; nb < 4; nb++)
                    mma_f16(c[ma][nb], a[ma], b[nb]);
        }
    }

    #pragma unroll
    for (int ma = 0; ma < 4; ma++) {
        int r = m0 + wm * 64 + ma * 16 + gid;
        #pragma unroll
        for (int nb = 0; nb < 4; nb++) {
            int col = n0 + wn * 32 + nb * 8 + 2 * tig;
            float b0 = bias[col], b1 = bias[col + 1];
            if (HALF_OUT) {
                __half* C = (__half*)Cv;
                __half2 v0 = __floats2half2_rn(c[ma][nb][0] + b0, c[ma][nb][1] + b1);
                __half2 v1 = __floats2half2_rn(c[ma][nb][2] + b0, c[ma][nb][3] + b1);
                *(__half2*)&C[(long)r * 1024 + col]       = v0;
                *(__half2*)&C[(long)(r + 8) * 1024 + col] = v1;
            } else {
                float* C = (float*)Cv;
                *(float2*)&C[(long)r * 1024 + col] =
                    make_float2(c[ma][nb][0] + b0, c[ma][nb][1] + b1);
                *(float2*)&C[(long)(r + 8) * 1024 + col] =
                    make_float2(c[ma][nb][2] + b0, c[ma][nb][3] + b1);
            }
        }
    }
}

__global__ __launch_bounds__(256, 2) void gemm_qkv(
    const float* __restrict__ bq, const float* __restrict__ bk, const float* __restrict__ bv)
{
    if (blockIdx.z == 0)      gemm_body<true>(g_xq, g_wq, bq, g_q);
    else if (blockIdx.z == 1) gemm_body<true>(g_xk, g_wk, bk, g_k);
    else                      gemm_body<true>(g_xv, g_wv, bv, g_v);
}

__global__ __launch_bounds__(256, 2) void gemm_out(
    const float* __restrict__ bo, float* __restrict__ C)
{
    gemm_body<false>(g_ao, g_wo, bo, C);
}

// ---------------------------------------------------------------------------
// Flash attention: fp16 mma, register-resident P, cp.async K/mask double
// buffering, register-prefetched V, CF Vt (stride 72).
// Block = 128 rows of one (n,h), BC=64 cols. Row r = ql*2+x, col c = kl*2+y.
// ---------------------------------------------------------------------------
#define ATTN_SMEM_BYTES ((2*64*36 + 2*64*36 + 32*72 + 128*36) * 4)   // 64512

__global__ __launch_bounds__(256, 2) void attn_mma(const int* __restrict__ mask)
{
    extern __shared__ __align__(16) unsigned smA[];
    unsigned* Ks = smA;                        // 2 bufs [64][36] half2
    int* msk = (int*)(Ks + 2 * 64 * 36);       // 2 bufs [64][36] int
    unsigned* Vt = (unsigned*)(msk + 2 * 64 * 36);  // [c2:32][72] half2 pairs-along-c
    unsigned* Qs = Vt + 32 * 72;               // [row:128][36] half2

    const int nh = blockIdx.y, n = nh >> 3, h = nh & 7;
    const int bx = blockIdx.x;
    const int tid = threadIdx.x;
    const int warp = tid >> 5, lane = tid & 31;
    const int gid = lane >> 2, tig = lane & 3;
    const int r0 = warp * 16 + gid, r1 = r0 + 8;
    const uint32_t ks_smb = smem_u32(Ks);
    const uint32_t mk_smb = smem_u32(msk);

    const __half2 sc2 = __floats2half2_rn(SCALE, SCALE);

    // cp.async prefetch of K + mask tile t into buffer t&1
    auto issue_tile = [&](int t) {
        const int buf = t & 1;
        const uint32_t kb = ks_smb + buf * (64 * 36 * 4);
        const uint32_t mb = mk_smb + buf * (64 * 36 * 4);
        #pragma unroll
        for (int u = 0; u < 2; u++) {
            int chunk = tid + 256 * u;
            int cc = chunk >> 3, qq = chunk & 7;
            int cg = t * 64 + cc;
            int kl = cg >> 1, y = cg & 1;
            cp16(kb + (cc * 36 + qq * 4) * 4,
                 &g_k[(long)(n * SEQ + kl) * DQ + y * 512 + h * 64 + qq * 8]);
        }
        #pragma unroll
        for (int u = 0; u < 2; u++) {
            int chunk = tid + 256 * u;
            int qlr = chunk >> 3, qq = chunk & 7;
            cp16(mb + (qlr * 36 + qq * 4) * 4,
                 &mask[(long)(n * SEQ + bx * 64 + qlr) * SEQ + t * 32 + qq * 4]);
        }
        CP_COMMIT();
    };

    // Stage Q (pre-scaled, half2): 128 rows x 16 groups of 4 halves
    #pragma unroll
    for (int u = 0; u < 8; u++) {
        int idx = tid + 256 * u;
        int row = idx >> 4, d = (idx & 15) * 4;
        int rg = bx * 128 + row;
        int ql = rg >> 1, x = rg & 1;
        uint2 v = *(const uint2*)&g_q[(long)(n * SEQ + ql) * DQ + x * 512 + h * 64 + d];
        __half2 h0 = __hmul2(*(__half2*)&v.x, sc2);
        __half2 h1 = __hmul2(*(__half2*)&v.y, sc2);
        Qs[row * 36 + d / 2]     = *(unsigned*)&h0;
        Qs[row * 36 + d / 2 + 1] = *(unsigned*)&h1;
    }
    issue_tile(0);
    __syncthreads();
    unsigned q[4][4];
    #pragma unroll
    for (int s = 0; s < 4; s++) {
        q[s][0] = Qs[r0 * 36 + 8 * s + tig];
        q[s][1] = Qs[r1 * 36 + 8 * s + tig];
        q[s][2] = Qs[r0 * 36 + 8 * s + tig + 4];
        q[s][3] = Qs[r1 * 36 + 8 * s + tig + 4];
    }

    float o[8][4] = {};
    float m0 = -INFINITY, m1 = -INFINITY, l0 = 0.f, l1 = 0.f;
    const int qll0 = r0 >> 1, qll1 = qll0 + 4;

    // Per-thread V prefetch coordinates (same for every tile)
    const int v_c2 = tid >> 4;                  // 0..15  (+16 for u=1)
    const int v_d4 = (tid & 15) * 4;

    for (int t = 0; t < 16; t++) {
        CP_WAIT0();
        __syncthreads();   // K/msk buf t ready; all warps done with Vt of t-1
        if (t + 1 < 16) issue_tile(t + 1);

        // Prefetch V into registers (latency hidden behind S-gemm + softmax)
        uint2 vlo[2], vhi[2];
        #pragma unroll
        for (int u = 0; u < 2; u++) {
            int kl = t * 32 + v_c2 + 16 * u;
            long base = (long)(n * SEQ + kl) * DQ + h * 64 + v_d4;
            vlo[u] = *(const uint2*)&g_v[base];          // y=0 (even c)
            vhi[u] = *(const uint2*)&g_v[base + 512];    // y=1 (odd c)
        }

        const unsigned* Kb = Ks + (t & 1) * (64 * 36);
        const int* Mb = msk + (t & 1) * (64 * 36);

        // S(128x64) = Q K^T  (fp16, 4 k16-steps)
        float s[8][4] = {};
        #pragma unroll
        for (int ks = 0; ks < 4; ks++) {
            #pragma unroll
            for (int j = 0; j < 8; j++) {
                unsigned b[2];
                b[0] = Kb[(8 * j + gid) * 36 + 8 * ks + tig];
                b[1] = Kb[(8 * j + gid) * 36 + 8 * ks + tig + 4];
                mma_f16(s[j], q[ks], b);
            }
        }

        // Mask + online softmax (rows r0, r1 per thread)
        float mx0 = m0, mx1 = m1;
        #pragma unroll
        for (int j = 0; j < 8; j++) {
            int klc = 4 * j + tig;
            bool k0m = Mb[qll0 * 36 + klc] != 0;
            bool k1m = Mb[qll1 * 36 + klc] != 0;
            s[j][0] = k0m ? s[j][0] : NEG;
            s[j][1] = k0m ? s[j][1] : NEG;
            s[j][2] = k1m ? s[j][2] : NEG;
            s[j][3] = k1m ? s[j][3] : NEG;
            mx0 = fmaxf(mx0, fmaxf(s[j][0], s[j][1]));
            mx1 = fmaxf(mx1, fmaxf(s[j][2], s[j][3]));
        }
        mx0 = fmaxf(mx0, __shfl_xor_sync(0xffffffffu, mx0, 1));
        mx0 = fmaxf(mx0, __shfl_xor_sync(0xffffffffu, mx0, 2));
        mx1 = fmaxf(mx1, __shfl_xor_sync(0xffffffffu, mx1, 1));
        mx1 = fmaxf(mx1, __shfl_xor_sync(0xffffffffu, mx1, 2));
        float a0 = __expf(m0 - mx0), a1 = __expf(m1 - mx1);
        float sum0 = 0.f, sum1 = 0.f;
        #pragma unroll
        for (int j = 0; j < 8; j++) {
            s[j][0] = __expf(s[j][0] - mx0);
            s[j][1] = __expf(s[j][1] - mx0);
            s[j][2] = __expf(s[j][2] - mx1);
            s[j][3] = __expf(s[j][3] - mx1);
            sum0 += s[j][0] + s[j][1];
            sum1 += s[j][2] + s[j][3];
        }
        sum0 += __shfl_xor_sync(0xffffffffu, sum0, 1);
        sum0 += __shfl_xor_sync(0xffffffffu, sum0, 2);
        sum1 += __shfl_xor_sync(0xffffffffu, sum1, 1);
        sum1 += __shfl_xor_sync(0xffffffffu, sum1, 2);
        l0 = l0 * a0 + sum0; l1 = l1 * a1 + sum1;
        m0 = mx0; m1 = mx1;
        #pragma unroll
        for (int j = 0; j < 8; j++) {
            o[j][0] *= a0; o[j][1] *= a0; o[j][2] *= a1; o[j][3] *= a1;
        }

        // Repack prefetched V into Vt: Vt[c2][d] = half2{ V[2c2][d], V[2c2+1][d] }
        #pragma unroll
        for (int u = 0; u < 2; u++) {
            __half2 l0h = *(__half2*)&vlo[u].x, l1h = *(__half2*)&vlo[u].y;
            __half2 h0h = *(__half2*)&vhi[u].x, h1h = *(__half2*)&vhi[u].y;
            __half2 p0 = __halves2half2(__low2half(l0h),  __low2half(h0h));
            __half2 p1 = __halves2half2(__high2half(l0h), __high2half(h0h));
            __half2 p2 = __halves2half2(__low2half(l1h),  __low2half(h1h));
            __half2 p3 = __halves2half2(__high2half(l1h), __high2half(h1h));
            *(uint4*)&Vt[(v_c2 + 16 * u) * 72 + v_d4] = make_uint4(
                *(unsigned*)&p0, *(unsigned*)&p1, *(unsigned*)&p2, *(unsigned*)&p3);
        }
        __syncthreads();   // Vt ready

        // O += P V (fp16, P fragments built in registers)
        #pragma unroll
        for (int ks = 0; ks < 4; ks++) {
            unsigned a[4];
            a[0] = pack_h2(s[2 * ks][0],     s[2 * ks][1]);
            a[1] = pack_h2(s[2 * ks][2],     s[2 * ks][3]);
            a[2] = pack_h2(s[2 * ks + 1][0], s[2 * ks + 1][1]);
            a[3] = pack_h2(s[2 * ks + 1][2], s[2 * ks + 1][3]);
            #pragma unroll
            for (int j = 0; j < 8; j++) {
                unsigned b[2];
                b[0] = Vt[(8 * ks + tig) * 72 + 8 * j + gid];
                b[1] = Vt[(8 * ks + tig + 4) * 72 + 8 * j + gid];
                mma_f16(o[j], a, b);
            }
        }
    }

    // Normalize + store (half, consumed by gemm_out)
    float inv0 = 1.f / l0, inv1 = 1.f / l1;
    int rg0 = bx * 128 + r0, rg1 = rg0 + 8;
    int ql0 = rg0 >> 1, x0 = rg0 & 1;
    int ql1 = rg1 >> 1, x1 = rg1 & 1;
    __half* out0 = &g_ao[(long)(n * SEQ + ql0) * DQ + x0 * 512 + h * 64];
    __half* out1 = &g_ao[(long)(n * SEQ + ql1) * DQ + x1 * 512 + h * 64];
    #pragma unroll
    for (int j = 0; j < 8; j++) {
        *(__half2*)&out0[8 * j + 2 * tig] = __floats2half2_rn(o[j][0] * inv0, o[j][1] * inv0);
        *(__half2*)&out1[8 * j + 2 * tig] = __floats2half2_rn(o[j][2] * inv1, o[j][3] * inv1);
    }
}

// ---------------------------------------------------------------------------
extern "C" void kernel_launch(void* const* d_in, const int* in_sizes, int n_in,
                              void* d_out, int out_size)
{
    const float* query = (const float*)d_in[0];
    const float* key   = (const float*)d_in[1];
    const float* value = (const float*)d_in[2];
    const int*   mask  = (const int*)  d_in[3];
    const float* Wv    = (const float*)d_in[4];
    const float* bv    = (const float*)d_in[5];
    const float* Wk    = (const float*)d_in[6];
    const float* bk    = (const float*)d_in[7];
    const float* Wq    = (const float*)d_in[8];
    const float* bq    = (const float*)d_in[9];
    const float* Wo    = (const float*)d_in[10];
    const float* bo    = (const float*)d_in[11];
    float* out = (float*)d_out;

    static bool attr_set = false;
    if (!attr_set) {
        cudaFuncSetAttribute(attn_mma, cudaFuncAttributeMaxDynamicSharedMemorySize,
                             ATTN_SMEM_BYTES);
        cudaFuncSetAttribute(gemm_qkv, cudaFuncAttributeMaxDynamicSharedMemorySize,
                             GEMM_SMEM);
        cudaFuncSetAttribute(gemm_out, cudaFuncAttributeMaxDynamicSharedMemorySize,
                             GEMM_SMEM);
        attr_set = true;
    }

    cvt_kernel<<<2048, 256>>>(query, key, value, Wv, Wk, Wq, Wo);
    gemm_qkv<<<dim3(8, 32, 3), 256, GEMM_SMEM>>>(bq, bk, bv);
    attn_mma<<<dim3(8, 64), 256, ATTN_SMEM_BYTES>>>(mask);
    gemm_out<<<dim3(8, 32), 256, GEMM_SMEM>>>(bo, out);
}

// round 10
// speedup vs baseline: 1.3358x; 1.0368x over previous
#include <cuda_runtime.h>
#include <cuda_fp16.h>
#include <math.h>
#include <cstdint>

#define SEQ    512
#define DQ     1024
#define MTOK   4096
#define SCALE  0.044194173824159216f   // 1/sqrt(512)
#define NEG    -4.4194174e18f          // -1e20 * SCALE

// Scratch (device globals; no allocation allowed)
__device__ __half g_xq[MTOK * DQ];   // converted inputs
__device__ __half g_xk[MTOK * DQ];
__device__ __half g_xv[MTOK * DQ];
__device__ __half g_wq[DQ * DQ];     // converted weights
__device__ __half g_wk[DQ * DQ];
__device__ __half g_wv[DQ * DQ];
__device__ __half g_wo[DQ * DQ];
__device__ __half g_q [MTOK * DQ];   // projections
__device__ __half g_k [MTOK * DQ];
__device__ __half g_v [MTOK * DQ];
__device__ __half g_ao[MTOK * DQ];   // attention output

// ---------------------------------------------------------------------------
// helpers
// ---------------------------------------------------------------------------
__device__ __forceinline__ void mma_f16(float* c, const unsigned* a, const unsigned* b) {
    asm volatile(
        "mma.sync.aligned.m16n8k16.row.col.f32.f16.f16.f32 "
        "{%0,%1,%2,%3}, {%4,%5,%6,%7}, {%8,%9}, {%0,%1,%2,%3};\n"
        : "+f"(c[0]), "+f"(c[1]), "+f"(c[2]), "+f"(c[3])
        : "r"(a[0]), "r"(a[1]), "r"(a[2]), "r"(a[3]), "r"(b[0]), "r"(b[1]));
}
__device__ __forceinline__ uint32_t smem_u32(const void* p) {
    uint32_t a;
    asm("{ .reg .u64 t; cvta.to.shared.u64 t, %1; cvt.u32.u64 %0, t; }" : "=r"(a) : "l"(p));
    return a;
}
__device__ __forceinline__ void cp16(uint32_t s, const void* g) {
    asm volatile("cp.async.cg.shared.global [%0], [%1], 16;" :: "r"(s), "l"(g));
}
#define CP_COMMIT() asm volatile("cp.async.commit_group;" ::: "memory")
#define CP_WAIT0()  asm volatile("cp.async.wait_group 0;" ::: "memory")
__device__ __forceinline__ unsigned pack_h2(float x, float y) {
    __half2 h = __floats2half2_rn(x, y);
    return *(unsigned*)&h;
}

// ---------------------------------------------------------------------------
// f32 -> f16 conversion of inputs and weights, one pass.
// ---------------------------------------------------------------------------
__global__ __launch_bounds__(256) void cvt_kernel(
    const float* __restrict__ q, const float* __restrict__ k, const float* __restrict__ v,
    const float* __restrict__ wv, const float* __restrict__ wk,
    const float* __restrict__ wq, const float* __restrict__ wo)
{
    const long stride = (long)gridDim.x * blockDim.x;
    for (long i = (long)blockIdx.x * blockDim.x + threadIdx.x; i < 4194304; i += stride) {
        const float* src; __half* dst; long off;
        if (i < 3145728) {
            int which = (int)(i >> 20);
            off = i & 1048575;
            src = which == 0 ? q : which == 1 ? k : v;
            dst = which == 0 ? g_xq : which == 1 ? g_xk : g_xv;
        } else {
            long j = i - 3145728;
            int which = (int)(j >> 18);
            off = j & 262143;
            src = which == 0 ? wv : which == 1 ? wk : which == 2 ? wq : wo;
            dst = which == 0 ? g_wv : which == 1 ? g_wk : which == 2 ? g_wq : g_wo;
        }
        float4 val = ((const float4*)src)[off];
        uint2 h;
        h.x = pack_h2(val.x, val.y);
        h.y = pack_h2(val.z, val.w);
        ((uint2*)dst)[off] = h;
    }
}

// ---------------------------------------------------------------------------
// Pipelined fp16 GEMM: C = A @ W^T + bias.
// 128x128 tile, BK=64, 3-stage cp.async ring, 256 thr / 8 warps (2x4),
// warp tile 64x32, stride-36 conflict-free fragments.
// Chunk loop fully unrolled -> constant smem offsets, better scheduling.
// ---------------------------------------------------------------------------
#define GSTG  4608                     // uints per tile stage (128*36)
#define GEMM_SMEM (6 * GSTG * 4)       // 110592 bytes

template<bool HALF_OUT>
__device__ __forceinline__ void gemm_body(
    const __half* __restrict__ A, const __half* __restrict__ W,
    const float* __restrict__ bias, void* Cv)
{
    extern __shared__ __align__(16) unsigned sm[];
    const int tid = threadIdx.x;
    const int warp = tid >> 5, lane = tid & 31;
    const int gid = lane >> 2, tig = lane & 3;
    const int wm = warp >> 2, wn = warp & 3;
    const int m0 = blockIdx.y * 128, n0 = blockIdx.x * 128;
    const uint32_t smb = smem_u32(sm);

    float c[4][4][4] = {};

    auto issue = [&](int stage) {
        const int buf = stage % 3;
        const long k0 = (long)stage * 64;
        const uint32_t ab = smb + buf * (GSTG * 4);
        const uint32_t bb = smb + 3 * (GSTG * 4) + buf * (GSTG * 4);
        #pragma unroll
        for (int u = 0; u < 4; u++) {
            int chunk = tid + 256 * u;
            int row = chunk >> 3, qq = chunk & 7;
            cp16(ab + (row * 36 + qq * 4) * 4, &A[(long)(m0 + row) * 1024 + k0 + qq * 8]);
        }
        #pragma unroll
        for (int u = 0; u < 4; u++) {
            int chunk = tid + 256 * u;
            int row = chunk >> 3, qq = chunk & 7;
            cp16(bb + (row * 36 + qq * 4) * 4, &W[(long)(n0 + row) * 1024 + k0 + qq * 8]);
        }
        CP_COMMIT();
    };

    issue(0);
    issue(1);

    #pragma unroll
    for (int ch = 0; ch < 16; ch++) {
        if (ch < 14) asm volatile("cp.async.wait_group 1;" ::: "memory");
        else         asm volatile("cp.async.wait_group 0;" ::: "memory");
        __syncthreads();
        if (ch + 2 < 16) issue(ch + 2);

        unsigned* Ab = sm + (ch % 3) * GSTG;
        unsigned* Bb = sm + 3 * GSTG + (ch % 3) * GSTG;
        #pragma unroll
        for (int s = 0; s < 4; s++) {
            const int k2 = s * 8;
            unsigned a[4][4], b[4][2];
            #pragma unroll
            for (int ma = 0; ma < 4; ma++) {
                int r = wm * 64 + ma * 16 + gid;
                a[ma][0] = Ab[r * 36 + k2 + tig];
                a[ma][1] = Ab[(r + 8) * 36 + k2 + tig];
                a[ma][2] = Ab[r * 36 + k2 + tig + 4];
                a[ma][3] = Ab[(r + 8) * 36 + k2 + tig + 4];
            }
            #pragma unroll
            for (int nb = 0; nb < 4; nb++) {
                int cc = wn * 32 + nb * 8 + gid;
                b[nb][0] = Bb[cc * 36 + k2 + tig];
                b[nb][1] = Bb[cc * 36 + k2 + tig + 4];
            }
            #pragma unroll
            for (int ma = 0; ma < 4; ma++)
                #pragma unroll
                for (int nb = 0; nb < 4; nb++)
                    mma_f16(c[ma][nb], a[ma], b[nb]);
        }
    }

    #pragma unroll
    for (int ma = 0; ma < 4; ma++) {
        int r = m0 + wm * 64 + ma * 16 + gid;
        #pragma unroll
        for (int nb = 0; nb < 4; nb++) {
            int col = n0 + wn * 32 + nb * 8 + 2 * tig;
            float b0 = bias[col], b1 = bias[col + 1];
            if (HALF_OUT) {
                __half* C = (__half*)Cv;
                __half2 v0 = __floats2half2_rn(c[ma][nb][0] + b0, c[ma][nb][1] + b1);
                __half2 v1 = __floats2half2_rn(c[ma][nb][2] + b0, c[ma][nb][3] + b1);
                *(__half2*)&C[(long)r * 1024 + col]       = v0;
                *(__half2*)&C[(long)(r + 8) * 1024 + col] = v1;
            } else {
                float* C = (float*)Cv;
                *(float2*)&C[(long)r * 1024 + col] =
                    make_float2(c[ma][nb][0] + b0, c[ma][nb][1] + b1);
                *(float2*)&C[(long)(r + 8) * 1024 + col] =
                    make_float2(c[ma][nb][2] + b0, c[ma][nb][3] + b1);
            }
        }
    }
}

__global__ __launch_bounds__(256, 2) void gemm_qkv(
    const float* __restrict__ bq, const float* __restrict__ bk, const float* __restrict__ bv)
{
    if (blockIdx.z == 0)      gemm_body<true>(g_xq, g_wq, bq, g_q);
    else if (blockIdx.z == 1) gemm_body<true>(g_xk, g_wk, bk, g_k);
    else                      gemm_body<true>(g_xv, g_wv, bv, g_v);
}

__global__ __launch_bounds__(256, 2) void gemm_out(
    const float* __restrict__ bo, float* __restrict__ C)
{
    gemm_body<false>(g_ao, g_wo, bo, C);
}

// ---------------------------------------------------------------------------
// Flash attention: fp16 mma, register-resident P, cp.async K/mask double
// buffering, register-prefetched V, CF Vt (stride 72).
// Fragment loads batched per k-step (load 16 uints, then 8 MMAs).
// Block = 128 rows of one (n,h), BC=64 cols. Row r = ql*2+x, col c = kl*2+y.
// ---------------------------------------------------------------------------
#define ATTN_SMEM_BYTES ((2*64*36 + 2*64*36 + 32*72 + 128*36) * 4)   // 64512

__global__ __launch_bounds__(256, 2) void attn_mma(const int* __restrict__ mask)
{
    extern __shared__ __align__(16) unsigned smA[];
    unsigned* Ks = smA;                        // 2 bufs [64][36] half2
    int* msk = (int*)(Ks + 2 * 64 * 36);       // 2 bufs [64][36] int
    unsigned* Vt = (unsigned*)(msk + 2 * 64 * 36);  // [c2:32][72] half2 pairs-along-c
    unsigned* Qs = Vt + 32 * 72;               // [row:128][36] half2

    const int nh = blockIdx.y, n = nh >> 3, h = nh & 7;
    const int bx = blockIdx.x;
    const int tid = threadIdx.x;
    const int warp = tid >> 5, lane = tid & 31;
    const int gid = lane >> 2, tig = lane & 3;
    const int r0 = warp * 16 + gid, r1 = r0 + 8;
    const uint32_t ks_smb = smem_u32(Ks);
    const uint32_t mk_smb = smem_u32(msk);

    const __half2 sc2 = __floats2half2_rn(SCALE, SCALE);

    // cp.async prefetch of K + mask tile t into buffer t&1
    auto issue_tile = [&](int t) {
        const int buf = t & 1;
        const uint32_t kb = ks_smb + buf * (64 * 36 * 4);
        const uint32_t mb = mk_smb + buf * (64 * 36 * 4);
        #pragma unroll
        for (int u = 0; u < 2; u++) {
            int chunk = tid + 256 * u;
            int cc = chunk >> 3, qq = chunk & 7;
            int cg = t * 64 + cc;
            int kl = cg >> 1, y = cg & 1;
            cp16(kb + (cc * 36 + qq * 4) * 4,
                 &g_k[(long)(n * SEQ + kl) * DQ + y * 512 + h * 64 + qq * 8]);
        }
        #pragma unroll
        for (int u = 0; u < 2; u++) {
            int chunk = tid + 256 * u;
            int qlr = chunk >> 3, qq = chunk & 7;
            cp16(mb + (qlr * 36 + qq * 4) * 4,
                 &mask[(long)(n * SEQ + bx * 64 + qlr) * SEQ + t * 32 + qq * 4]);
        }
        CP_COMMIT();
    };

    // Stage Q (pre-scaled, half2): 128 rows x 16 groups of 4 halves
    #pragma unroll
    for (int u = 0; u < 8; u++) {
        int idx = tid + 256 * u;
        int row = idx >> 4, d = (idx & 15) * 4;
        int rg = bx * 128 + row;
        int ql = rg >> 1, x = rg & 1;
        uint2 v = *(const uint2*)&g_q[(long)(n * SEQ + ql) * DQ + x * 512 + h * 64 + d];
        __half2 h0 = __hmul2(*(__half2*)&v.x, sc2);
        __half2 h1 = __hmul2(*(__half2*)&v.y, sc2);
        Qs[row * 36 + d / 2]     = *(unsigned*)&h0;
        Qs[row * 36 + d / 2 + 1] = *(unsigned*)&h1;
    }
    issue_tile(0);
    __syncthreads();
    unsigned q[4][4];
    #pragma unroll
    for (int s = 0; s < 4; s++) {
        q[s][0] = Qs[r0 * 36 + 8 * s + tig];
        q[s][1] = Qs[r1 * 36 + 8 * s + tig];
        q[s][2] = Qs[r0 * 36 + 8 * s + tig + 4];
        q[s][3] = Qs[r1 * 36 + 8 * s + tig + 4];
    }

    float o[8][4] = {};
    float m0 = -INFINITY, m1 = -INFINITY, l0 = 0.f, l1 = 0.f;
    const int qll0 = r0 >> 1, qll1 = qll0 + 4;

    // Per-thread V prefetch coordinates (same for every tile)
    const int v_c2 = tid >> 4;                  // 0..15  (+16 for u=1)
    const int v_d4 = (tid & 15) * 4;

    for (int t = 0; t < 16; t++) {
        CP_WAIT0();
        __syncthreads();   // K/msk buf t ready; all warps done with Vt of t-1
        if (t + 1 < 16) issue_tile(t + 1);

        // Prefetch V into registers (latency hidden behind S-gemm + softmax)
        uint2 vlo[2], vhi[2];
        #pragma unroll
        for (int u = 0; u < 2; u++) {
            int kl = t * 32 + v_c2 + 16 * u;
            long base = (long)(n * SEQ + kl) * DQ + h * 64 + v_d4;
            vlo[u] = *(const uint2*)&g_v[base];          // y=0 (even c)
            vhi[u] = *(const uint2*)&g_v[base + 512];    // y=1 (odd c)
        }

        const unsigned* Kb = Ks + (t & 1) * (64 * 36);
        const int* Mb = msk + (t & 1) * (64 * 36);

        // S(128x64) = Q K^T  (fp16, 4 k16-steps; fragment loads batched)
        float s[8][4] = {};
        #pragma unroll
        for (int ks = 0; ks < 4; ks++) {
            unsigned bb[8][2];
            #pragma unroll
            for (int j = 0; j < 8; j++) {
                bb[j][0] = Kb[(8 * j + gid) * 36 + 8 * ks + tig];
                bb[j][1] = Kb[(8 * j + gid) * 36 + 8 * ks + tig + 4];
            }
            #pragma unroll
            for (int j = 0; j < 8; j++)
                mma_f16(s[j], q[ks], bb[j]);
        }

        // Mask + online softmax (rows r0, r1 per thread)
        float mx0 = m0, mx1 = m1;
        #pragma unroll
        for (int j = 0; j < 8; j++) {
            int klc = 4 * j + tig;
            bool k0m = Mb[qll0 * 36 + klc] != 0;
            bool k1m = Mb[qll1 * 36 + klc] != 0;
            s[j][0] = k0m ? s[j][0] : NEG;
            s[j][1] = k0m ? s[j][1] : NEG;
            s[j][2] = k1m ? s[j][2] : NEG;
            s[j][3] = k1m ? s[j][3] : NEG;
            mx0 = fmaxf(mx0, fmaxf(s[j][0], s[j][1]));
            mx1 = fmaxf(mx1, fmaxf(s[j][2], s[j][3]));
        }
        mx0 = fmaxf(mx0, __shfl_xor_sync(0xffffffffu, mx0, 1));
        mx0 = fmaxf(mx0, __shfl_xor_sync(0xffffffffu, mx0, 2));
        mx1 = fmaxf(mx1, __shfl_xor_sync(0xffffffffu, mx1, 1));
        mx1 = fmaxf(mx1, __shfl_xor_sync(0xffffffffu, mx1, 2));
        float a0 = __expf(m0 - mx0), a1 = __expf(m1 - mx1);
        float sum0 = 0.f, sum1 = 0.f;
        #pragma unroll
        for (int j = 0; j < 8; j++) {
            s[j][0] = __expf(s[j][0] - mx0);
            s[j][1] = __expf(s[j][1] - mx0);
            s[j][2] = __expf(s[j][2] - mx1);
            s[j][3] = __expf(s[j][3] - mx1);
            sum0 += s[j][0] + s[j][1];
            sum1 += s[j][2] + s[j][3];
        }
        sum0 += __shfl_xor_sync(0xffffffffu, sum0, 1);
        sum0 += __shfl_xor_sync(0xffffffffu, sum0, 2);
        sum1 += __shfl_xor_sync(0xffffffffu, sum1, 1);
        sum1 += __shfl_xor_sync(0xffffffffu, sum1, 2);
        l0 = l0 * a0 + sum0; l1 = l1 * a1 + sum1;
        m0 = mx0; m1 = mx1;
        #pragma unroll
        for (int j = 0; j < 8; j++) {
            o[j][0] *= a0; o[j][1] *= a0; o[j][2] *= a1; o[j][3] *= a1;
        }

        // Repack prefetched V into Vt: Vt[c2][d] = half2{ V[2c2][d], V[2c2+1][d] }
        #pragma unroll
        for (int u = 0; u < 2; u++) {
            __half2 l0h = *(__half2*)&vlo[u].x, l1h = *(__half2*)&vlo[u].y;
            __half2 h0h = *(__half2*)&vhi[u].x, h1h = *(__half2*)&vhi[u].y;
            __half2 p0 = __halves2half2(__low2half(l0h),  __low2half(h0h));
            __half2 p1 = __halves2half2(__high2half(l0h), __high2half(h0h));
            __half2 p2 = __halves2half2(__low2half(l1h),  __low2half(h1h));
            __half2 p3 = __halves2half2(__high2half(l1h), __high2half(h1h));
            *(uint4*)&Vt[(v_c2 + 16 * u) * 72 + v_d4] = make_uint4(
                *(unsigned*)&p0, *(unsigned*)&p1, *(unsigned*)&p2, *(unsigned*)&p3);
        }
        __syncthreads();   // Vt ready

        // O += P V (fp16, P fragments in registers; V fragment loads batched)
        #pragma unroll
        for (int ks = 0; ks < 4; ks++) {
            unsigned a[4];
            a[0] = pack_h2(s[2 * ks][0],     s[2 * ks][1]);
            a[1] = pack_h2(s[2 * ks][2],     s[2 * ks][3]);
            a[2] = pack_h2(s[2 * ks + 1][0], s[2 * ks + 1][1]);
            a[3] = pack_h2(s[2 * ks + 1][2], s[2 * ks + 1][3]);
            unsigned bb[8][2];
            #pragma unroll
            for (int j = 0; j < 8; j++) {
                bb[j][0] = Vt[(8 * ks + tig) * 72 + 8 * j + gid];
                bb[j][1] = Vt[(8 * ks + tig + 4) * 72 + 8 * j + gid];
            }
            #pragma unroll
            for (int j = 0; j < 8; j++)
                mma_f16(o[j], a, bb[j]);
        }
    }

    // Normalize + store (half, consumed by gemm_out)
    float inv0 = 1.f / l0, inv1 = 1.f / l1;
    int rg0 = bx * 128 + r0, rg1 = rg0 + 8;
    int ql0 = rg0 >> 1, x0 = rg0 & 1;
    int ql1 = rg1 >> 1, x1 = rg1 & 1;
    __half* out0 = &g_ao[(long)(n * SEQ + ql0) * DQ + x0 * 512 + h * 64];
    __half* out1 = &g_ao[(long)(n * SEQ + ql1) * DQ + x1 * 512 + h * 64];
    #pragma unroll
    for (int j = 0; j < 8; j++) {
        *(__half2*)&out0[8 * j + 2 * tig] = __floats2half2_rn(o[j][0] * inv0, o[j][1] * inv0);
        *(__half2*)&out1[8 * j + 2 * tig] = __floats2half2_rn(o[j][2] * inv1, o[j][3] * inv1);
    }
}

// ---------------------------------------------------------------------------
extern "C" void kernel_launch(void* const* d_in, const int* in_sizes, int n_in,
                              void* d_out, int out_size)
{
    const float* query = (const float*)d_in[0];
    const float* key   = (const float*)d_in[1];
    const float* value = (const float*)d_in[2];
    const int*   mask  = (const int*)  d_in[3];
    const float* Wv    = (const float*)d_in[4];
    const float* bv    = (const float*)d_in[5];
    const float* Wk    = (const float*)d_in[6];
    const float* bk    = (const float*)d_in[7];
    const float* Wq    = (const float*)d_in[8];
    const float* bq    = (const float*)d_in[9];
    const float* Wo    = (const float*)d_in[10];
    const float* bo    = (const float*)d_in[11];
    float* out = (float*)d_out;

    static bool attr_set = false;
    if (!attr_set) {
        cudaFuncSetAttribute(attn_mma, cudaFuncAttributeMaxDynamicSharedMemorySize,
                             ATTN_SMEM_BYTES);
        cudaFuncSetAttribute(gemm_qkv, cudaFuncAttributeMaxDynamicSharedMemorySize,
                             GEMM_SMEM);
        cudaFuncSetAttribute(gemm_out, cudaFuncAttributeMaxDynamicSharedMemorySize,
                             GEMM_SMEM);
        attr_set = true;
    }

    cvt_kernel<<<2048, 256>>>(query, key, value, Wv, Wk, Wq, Wo);
    gemm_qkv<<<dim3(8, 32, 3), 256, GEMM_SMEM>>>(bq, bk, bv);
    attn_mma<<<dim3(8, 64), 256, ATTN_SMEM_BYTES>>>(mask);
    gemm_out<<<dim3(8, 32), 256, GEMM_SMEM>>>(bo, out);
}

// round 11
// speedup vs baseline: 1.4577x; 1.0912x over previous
#include <cuda_runtime.h>
#include <cuda_fp16.h>
#include <math.h>
#include <cstdint>

#define SEQ    512
#define DQ     1024
#define MTOK   4096
#define SCALE  0.044194173824159216f   // 1/sqrt(512)
#define NEG    -4.4194174e18f          // -1e20 * SCALE

// Scratch (device globals; no allocation allowed)
// g_x* and g_w* are stored LAYER-1 PERMUTED: within each 16-half group,
// uint order [0,4,1,5,2,6,3,7] (mma frag pairs adjacent).
// g_q/g_k/g_v are row-major (consumed by attention).
// g_ao is layer-1 permuted (consumed only by gemm_out).
__device__ __half g_xq[MTOK * DQ];
__device__ __half g_xk[MTOK * DQ];
__device__ __half g_xv[MTOK * DQ];
__device__ __half g_wq[DQ * DQ];
__device__ __half g_wk[DQ * DQ];
__device__ __half g_wv[DQ * DQ];
__device__ __half g_wo[DQ * DQ];
__device__ __half g_q [MTOK * DQ];
__device__ __half g_k [MTOK * DQ];
__device__ __half g_v [MTOK * DQ];
__device__ __half g_ao[MTOK * DQ];

// ---------------------------------------------------------------------------
// helpers
// ---------------------------------------------------------------------------
__device__ __forceinline__ void mma_f16(float* c, const unsigned* a, const unsigned* b) {
    asm volatile(
        "mma.sync.aligned.m16n8k16.row.col.f32.f16.f16.f32 "
        "{%0,%1,%2,%3}, {%4,%5,%6,%7}, {%8,%9}, {%0,%1,%2,%3};\n"
        : "+f"(c[0]), "+f"(c[1]), "+f"(c[2]), "+f"(c[3])
        : "r"(a[0]), "r"(a[1]), "r"(a[2]), "r"(a[3]), "r"(b[0]), "r"(b[1]));
}
__device__ __forceinline__ uint32_t smem_u32(const void* p) {
    uint32_t a;
    asm("{ .reg .u64 t; cvta.to.shared.u64 t, %1; cvt.u32.u64 %0, t; }" : "=r"(a) : "l"(p));
    return a;
}
__device__ __forceinline__ void cp16(uint32_t s, const void* g) {
    asm volatile("cp.async.cg.shared.global [%0], [%1], 16;" :: "r"(s), "l"(g));
}
#define CP_COMMIT() asm volatile("cp.async.commit_group;" ::: "memory")
#define CP_WAIT0()  asm volatile("cp.async.wait_group 0;" ::: "memory")
__device__ __forceinline__ unsigned pack_h2(float x, float y) {
    __half2 h = __floats2half2_rn(x, y);
    return *(unsigned*)&h;
}

// ---------------------------------------------------------------------------
// f32 -> f16 conversion + layer-1 permutation, one pass.
// Each thread handles one 16-half group (16 f32 in, 2 uint4 out).
// Logical uints j0..j7 -> positions [j0,j4,j1,j5,j2,j6,j3,j7].
// Groups: inputs 3 x 2^18, weights 4 x 2^16. Total 1048576.
// ---------------------------------------------------------------------------
__global__ __launch_bounds__(256) void cvt_kernel(
    const float* __restrict__ q, const float* __restrict__ k, const float* __restrict__ v,
    const float* __restrict__ wv, const float* __restrict__ wk,
    const float* __restrict__ wq, const float* __restrict__ wo)
{
    const long stride = (long)gridDim.x * blockDim.x;
    for (long g = (long)blockIdx.x * blockDim.x + threadIdx.x; g < 1048576; g += stride) {
        const float* src; __half* dst; long goff;
        if (g < 786432) {
            int which = (int)(g >> 18);
            goff = g & 262143;
            src = which == 0 ? q : which == 1 ? k : v;
            dst = which == 0 ? g_xq : which == 1 ? g_xk : g_xv;
        } else {
            long j = g - 786432;
            int which = (int)(j >> 16);
            goff = j & 65535;
            src = which == 0 ? wv : which == 1 ? wk : which == 2 ? wq : wo;
            dst = which == 0 ? g_wv : which == 1 ? g_wk : which == 2 ? g_wq : g_wo;
        }
        const float4* s4 = (const float4*)(src + goff * 16);
        float4 f0 = s4[0], f1 = s4[1], f2 = s4[2], f3 = s4[3];
        uint4 o0, o1;
        o0.x = pack_h2(f0.x, f0.y);  // j0
        o0.y = pack_h2(f2.x, f2.y);  // j4
        o0.z = pack_h2(f0.z, f0.w);  // j1
        o0.w = pack_h2(f2.z, f2.w);  // j5
        o1.x = pack_h2(f1.x, f1.y);  // j2
        o1.y = pack_h2(f3.x, f3.y);  // j6
        o1.z = pack_h2(f1.z, f1.w);  // j3
        o1.w = pack_h2(f3.z, f3.w);  // j7
        uint4* d4 = (uint4*)(dst + goff * 16);
        d4[0] = o0;
        d4[1] = o1;
    }
}

// ---------------------------------------------------------------------------
// Pipelined fp16 GEMM: C = A @ W^T + bias.
// A, W are layer-1 permuted in gmem. Smem: 128 rows x 128B (no pad),
// layer-2 XOR swizzle phys_uint = pos ^ ((row&3)<<3) -> LDS.64 frags CF.
// 128x128 tile, BK=64, 3-stage cp.async ring, 256 thr / 8 warps (2x4),
// warp tile 64x32. Per k-step: 8 LDS.64 (A) + 4 LDS.64 (B).
// ---------------------------------------------------------------------------
#define GSTG  4096                     // uints per tile stage (128*32)
#define GEMM_SMEM (6 * GSTG * 4)       // 98304 bytes

template<bool HALF_OUT>
__device__ __forceinline__ void gemm_body(
    const __half* __restrict__ A, const __half* __restrict__ W,
    const float* __restrict__ bias, void* Cv)
{
    extern __shared__ __align__(16) unsigned sm[];
    const int tid = threadIdx.x;
    const int warp = tid >> 5, lane = tid & 31;
    const int gid = lane >> 2, tig = lane & 3;
    const int wm = warp >> 2, wn = warp & 3;
    const int m0 = blockIdx.y * 128, n0 = blockIdx.x * 128;
    const uint32_t smb = smem_u32(sm);

    float c[4][4][4] = {};

    auto issue = [&](int stage) {
        const int buf = stage % 3;
        const long k0 = (long)stage * 64;
        const uint32_t ab = smb + buf * (GSTG * 4);
        const uint32_t bb = smb + 3 * (GSTG * 4) + buf * (GSTG * 4);
        #pragma unroll
        for (int u = 0; u < 4; u++) {
            int chunk = tid + 256 * u;
            int row = chunk >> 3, qq = chunk & 7;
            uint32_t doff = (row * 32 + 4 * (qq ^ ((row & 3) << 1))) * 4;
            cp16(ab + doff, &A[(long)(m0 + row) * 1024 + k0 + qq * 8]);
        }
        #pragma unroll
        for (int u = 0; u < 4; u++) {
            int chunk = tid + 256 * u;
            int row = chunk >> 3, qq = chunk & 7;
            uint32_t doff = (row * 32 + 4 * (qq ^ ((row & 3) << 1))) * 4;
            cp16(bb + doff, &W[(long)(n0 + row) * 1024 + k0 + qq * 8]);
        }
        CP_COMMIT();
    };

    issue(0);
    issue(1);

    #pragma unroll
    for (int ch = 0; ch < 16; ch++) {
        if (ch < 14) asm volatile("cp.async.wait_group 1;" ::: "memory");
        else         asm volatile("cp.async.wait_group 0;" ::: "memory");
        __syncthreads();
        if (ch + 2 < 16) issue(ch + 2);

        unsigned* Ab = sm + (ch % 3) * GSTG;
        unsigned* Bb = sm + 3 * GSTG + (ch % 3) * GSTG;
        #pragma unroll
        for (int s = 0; s < 4; s++) {
            // swizzled pair offset: rows here all have row&3 == gid&3
            const int po = 8 * (s ^ (gid & 3)) + 2 * tig;
            unsigned a[4][4], b[4][2];
            #pragma unroll
            for (int ma = 0; ma < 4; ma++) {
                int r = wm * 64 + ma * 16 + gid;
                uint2 A1 = *(const uint2*)&Ab[r * 32 + po];        // {a0, a2}
                uint2 A2 = *(const uint2*)&Ab[(r + 8) * 32 + po];  // {a1, a3}
                a[ma][0] = A1.x; a[ma][1] = A2.x; a[ma][2] = A1.y; a[ma][3] = A2.y;
            }
            #pragma unroll
            for (int nb = 0; nb < 4; nb++) {
                int cc = wn * 32 + nb * 8 + gid;
                uint2 B1 = *(const uint2*)&Bb[cc * 32 + po];       // {b0, b1}
                b[nb][0] = B1.x; b[nb][1] = B1.y;
            }
            #pragma unroll
            for (int ma = 0; ma < 4; ma++)
                #pragma unroll
                for (int nb = 0; nb < 4; nb++)
                    mma_f16(c[ma][nb], a[ma], b[nb]);
        }
    }

    #pragma unroll
    for (int ma = 0; ma < 4; ma++) {
        int r = m0 + wm * 64 + ma * 16 + gid;
        #pragma unroll
        for (int nb = 0; nb < 4; nb++) {
            int col = n0 + wn * 32 + nb * 8 + 2 * tig;
            float b0 = bias[col], b1 = bias[col + 1];
            if (HALF_OUT) {
                __half* C = (__half*)Cv;
                __half2 v0 = __floats2half2_rn(c[ma][nb][0] + b0, c[ma][nb][1] + b1);
                __half2 v1 = __floats2half2_rn(c[ma][nb][2] + b0, c[ma][nb][3] + b1);
                *(__half2*)&C[(long)r * 1024 + col]       = v0;
                *(__half2*)&C[(long)(r + 8) * 1024 + col] = v1;
            } else {
                float* C = (float*)Cv;
                *(float2*)&C[(long)r * 1024 + col] =
                    make_float2(c[ma][nb][0] + b0, c[ma][nb][1] + b1);
                *(float2*)&C[(long)(r + 8) * 1024 + col] =
                    make_float2(c[ma][nb][2] + b0, c[ma][nb][3] + b1);
            }
        }
    }
}

__global__ __launch_bounds__(256, 2) void gemm_qkv(
    const float* __restrict__ bq, const float* __restrict__ bk, const float* __restrict__ bv)
{
    if (blockIdx.z == 0)      gemm_body<true>(g_xq, g_wq, bq, g_q);
    else if (blockIdx.z == 1) gemm_body<true>(g_xk, g_wk, bk, g_k);
    else                      gemm_body<true>(g_xv, g_wv, bv, g_v);
}

__global__ __launch_bounds__(256, 2) void gemm_out(
    const float* __restrict__ bo, float* __restrict__ C)
{
    gemm_body<false>(g_ao, g_wo, bo, C);
}

// ---------------------------------------------------------------------------
// Flash attention (mainloop identical to R10): fp16 mma, register P,
// cp.async K/mask double buffering, register-prefetched V, CF Vt.
// Epilogue writes g_ao LAYER-1 PERMUTED (consumed only by gemm_out).
// ---------------------------------------------------------------------------
#define ATTN_SMEM_BYTES ((2*64*36 + 2*64*36 + 32*72 + 128*36) * 4)   // 64512

__global__ __launch_bounds__(256, 2) void attn_mma(const int* __restrict__ mask)
{
    extern __shared__ __align__(16) unsigned smA[];
    unsigned* Ks = smA;                        // 2 bufs [64][36] half2
    int* msk = (int*)(Ks + 2 * 64 * 36);       // 2 bufs [64][36] int
    unsigned* Vt = (unsigned*)(msk + 2 * 64 * 36);  // [c2:32][72] half2 pairs-along-c
    unsigned* Qs = Vt + 32 * 72;               // [row:128][36] half2

    const int nh = blockIdx.y, n = nh >> 3, h = nh & 7;
    const int bx = blockIdx.x;
    const int tid = threadIdx.x;
    const int warp = tid >> 5, lane = tid & 31;
    const int gid = lane >> 2, tig = lane & 3;
    const int r0 = warp * 16 + gid, r1 = r0 + 8;
    const uint32_t ks_smb = smem_u32(Ks);
    const uint32_t mk_smb = smem_u32(msk);

    const __half2 sc2 = __floats2half2_rn(SCALE, SCALE);

    auto issue_tile = [&](int t) {
        const int buf = t & 1;
        const uint32_t kb = ks_smb + buf * (64 * 36 * 4);
        const uint32_t mb = mk_smb + buf * (64 * 36 * 4);
        #pragma unroll
        for (int u = 0; u < 2; u++) {
            int chunk = tid + 256 * u;
            int cc = chunk >> 3, qq = chunk & 7;
            int cg = t * 64 + cc;
            int kl = cg >> 1, y = cg & 1;
            cp16(kb + (cc * 36 + qq * 4) * 4,
                 &g_k[(long)(n * SEQ + kl) * DQ + y * 512 + h * 64 + qq * 8]);
        }
        #pragma unroll
        for (int u = 0; u < 2; u++) {
            int chunk = tid + 256 * u;
            int qlr = chunk >> 3, qq = chunk & 7;
            cp16(mb + (qlr * 36 + qq * 4) * 4,
                 &mask[(long)(n * SEQ + bx * 64 + qlr) * SEQ + t * 32 + qq * 4]);
        }
        CP_COMMIT();
    };

    #pragma unroll
    for (int u = 0; u < 8; u++) {
        int idx = tid + 256 * u;
        int row = idx >> 4, d = (idx & 15) * 4;
        int rg = bx * 128 + row;
        int ql = rg >> 1, x = rg & 1;
        uint2 v = *(const uint2*)&g_q[(long)(n * SEQ + ql) * DQ + x * 512 + h * 64 + d];
        __half2 h0 = __hmul2(*(__half2*)&v.x, sc2);
        __half2 h1 = __hmul2(*(__half2*)&v.y, sc2);
        Qs[row * 36 + d / 2]     = *(unsigned*)&h0;
        Qs[row * 36 + d / 2 + 1] = *(unsigned*)&h1;
    }
    issue_tile(0);
    __syncthreads();
    unsigned q[4][4];
    #pragma unroll
    for (int s = 0; s < 4; s++) {
        q[s][0] = Qs[r0 * 36 + 8 * s + tig];
        q[s][1] = Qs[r1 * 36 + 8 * s + tig];
        q[s][2] = Qs[r0 * 36 + 8 * s + tig + 4];
        q[s][3] = Qs[r1 * 36 + 8 * s + tig + 4];
    }

    float o[8][4] = {};
    float m0 = -INFINITY, m1 = -INFINITY, l0 = 0.f, l1 = 0.f;
    const int qll0 = r0 >> 1, qll1 = qll0 + 4;

    const int v_c2 = tid >> 4;
    const int v_d4 = (tid & 15) * 4;

    for (int t = 0; t < 16; t++) {
        CP_WAIT0();
        __syncthreads();
        if (t + 1 < 16) issue_tile(t + 1);

        uint2 vlo[2], vhi[2];
        #pragma unroll
        for (int u = 0; u < 2; u++) {
            int kl = t * 32 + v_c2 + 16 * u;
            long base = (long)(n * SEQ + kl) * DQ + h * 64 + v_d4;
            vlo[u] = *(const uint2*)&g_v[base];
            vhi[u] = *(const uint2*)&g_v[base + 512];
        }

        const unsigned* Kb = Ks + (t & 1) * (64 * 36);
        const int* Mb = msk + (t & 1) * (64 * 36);

        float s[8][4] = {};
        #pragma unroll
        for (int ks = 0; ks < 4; ks++) {
            unsigned bb[8][2];
            #pragma unroll
            for (int j = 0; j < 8; j++) {
                bb[j][0] = Kb[(8 * j + gid) * 36 + 8 * ks + tig];
                bb[j][1] = Kb[(8 * j + gid) * 36 + 8 * ks + tig + 4];
            }
            #pragma unroll
            for (int j = 0; j < 8; j++)
                mma_f16(s[j], q[ks], bb[j]);
        }

        float mx0 = m0, mx1 = m1;
        #pragma unroll
        for (int j = 0; j < 8; j++) {
            int klc = 4 * j + tig;
            bool k0m = Mb[qll0 * 36 + klc] != 0;
            bool k1m = Mb[qll1 * 36 + klc] != 0;
            s[j][0] = k0m ? s[j][0] : NEG;
            s[j][1] = k0m ? s[j][1] : NEG;
            s[j][2] = k1m ? s[j][2] : NEG;
            s[j][3] = k1m ? s[j][3] : NEG;
            mx0 = fmaxf(mx0, fmaxf(s[j][0], s[j][1]));
            mx1 = fmaxf(mx1, fmaxf(s[j][2], s[j][3]));
        }
        mx0 = fmaxf(mx0, __shfl_xor_sync(0xffffffffu, mx0, 1));
        mx0 = fmaxf(mx0, __shfl_xor_sync(0xffffffffu, mx0, 2));
        mx1 = fmaxf(mx1, __shfl_xor_sync(0xffffffffu, mx1, 1));
        mx1 = fmaxf(mx1, __shfl_xor_sync(0xffffffffu, mx1, 2));
        float a0 = __expf(m0 - mx0), a1 = __expf(m1 - mx1);
        float sum0 = 0.f, sum1 = 0.f;
        #pragma unroll
        for (int j = 0; j < 8; j++) {
            s[j][0] = __expf(s[j][0] - mx0);
            s[j][1] = __expf(s[j][1] - mx0);
            s[j][2] = __expf(s[j][2] - mx1);
            s[j][3] = __expf(s[j][3] - mx1);
            sum0 += s[j][0] + s[j][1];
            sum1 += s[j][2] + s[j][3];
        }
        sum0 += __shfl_xor_sync(0xffffffffu, sum0, 1);
        sum0 += __shfl_xor_sync(0xffffffffu, sum0, 2);
        sum1 += __shfl_xor_sync(0xffffffffu, sum1, 1);
        sum1 += __shfl_xor_sync(0xffffffffu, sum1, 2);
        l0 = l0 * a0 + sum0; l1 = l1 * a1 + sum1;
        m0 = mx0; m1 = mx1;
        #pragma unroll
        for (int j = 0; j < 8; j++) {
            o[j][0] *= a0; o[j][1] *= a0; o[j][2] *= a1; o[j][3] *= a1;
        }

        #pragma unroll
        for (int u = 0; u < 2; u++) {
            __half2 l0h = *(__half2*)&vlo[u].x, l1h = *(__half2*)&vlo[u].y;
            __half2 h0h = *(__half2*)&vhi[u].x, h1h = *(__half2*)&vhi[u].y;
            __half2 p0 = __halves2half2(__low2half(l0h),  __low2half(h0h));
            __half2 p1 = __halves2half2(__high2half(l0h), __high2half(h0h));
            __half2 p2 = __halves2half2(__low2half(l1h),  __low2half(h1h));
            __half2 p3 = __halves2half2(__high2half(l1h), __high2half(h1h));
            *(uint4*)&Vt[(v_c2 + 16 * u) * 72 + v_d4] = make_uint4(
                *(unsigned*)&p0, *(unsigned*)&p1, *(unsigned*)&p2, *(unsigned*)&p3);
        }
        __syncthreads();

        #pragma unroll
        for (int ks = 0; ks < 4; ks++) {
            unsigned a[4];
            a[0] = pack_h2(s[2 * ks][0],     s[2 * ks][1]);
            a[1] = pack_h2(s[2 * ks][2],     s[2 * ks][3]);
            a[2] = pack_h2(s[2 * ks + 1][0], s[2 * ks + 1][1]);
            a[3] = pack_h2(s[2 * ks + 1][2], s[2 * ks + 1][3]);
            unsigned bb[8][2];
            #pragma unroll
            for (int j = 0; j < 8; j++) {
                bb[j][0] = Vt[(8 * ks + tig) * 72 + 8 * j + gid];
                bb[j][1] = Vt[(8 * ks + tig + 4) * 72 + 8 * j + gid];
            }
            #pragma unroll
            for (int j = 0; j < 8; j++)
                mma_f16(o[j], a, bb[j]);
        }
    }

    // Normalize + store g_ao LAYER-1 PERMUTED:
    // logical uint u = 4j + tig  ->  phys half-offset 16*(j>>1) + 4*tig + 2*(j&1)
    float inv0 = 1.f / l0, inv1 = 1.f / l1;
    int rg0 = bx * 128 + r0, rg1 = rg0 + 8;
    int ql0 = rg0 >> 1, x0 = rg0 & 1;
    int ql1 = rg1 >> 1, x1 = rg1 & 1;
    __half* out0 = &g_ao[(long)(n * SEQ + ql0) * DQ + x0 * 512 + h * 64];
    __half* out1 = &g_ao[(long)(n * SEQ + ql1) * DQ + x1 * 512 + h * 64];
    #pragma unroll
    for (int j = 0; j < 8; j++) {
        int off = 16 * (j >> 1) + 4 * tig + 2 * (j & 1);
        *(__half2*)&out0[off] = __floats2half2_rn(o[j][0] * inv0, o[j][1] * inv0);
        *(__half2*)&out1[off] = __floats2half2_rn(o[j][2] * inv1, o[j][3] * inv1);
    }
}

// ---------------------------------------------------------------------------
extern "C" void kernel_launch(void* const* d_in, const int* in_sizes, int n_in,
                              void* d_out, int out_size)
{
    const float* query = (const float*)d_in[0];
    const float* key   = (const float*)d_in[1];
    const float* value = (const float*)d_in[2];
    const int*   mask  = (const int*)  d_in[3];
    const float* Wv    = (const float*)d_in[4];
    const float* bv    = (const float*)d_in[5];
    const float* Wk    = (const float*)d_in[6];
    const float* bk    = (const float*)d_in[7];
    const float* Wq    = (const float*)d_in[8];
    const float* bq    = (const float*)d_in[9];
    const float* Wo    = (const float*)d_in[10];
    const float* bo    = (const float*)d_in[11];
    float* out = (float*)d_out;

    static bool attr_set = false;
    if (!attr_set) {
        cudaFuncSetAttribute(attn_mma, cudaFuncAttributeMaxDynamicSharedMemorySize,
                             ATTN_SMEM_BYTES);
        cudaFuncSetAttribute(gemm_qkv, cudaFuncAttributeMaxDynamicSharedMemorySize,
                             GEMM_SMEM);
        cudaFuncSetAttribute(gemm_out, cudaFuncAttributeMaxDynamicSharedMemorySize,
                             GEMM_SMEM);
        attr_set = true;
    }

    cvt_kernel<<<2048, 256>>>(query, key, value, Wv, Wk, Wq, Wo);
    gemm_qkv<<<dim3(8, 32, 3), 256, GEMM_SMEM>>>(bq, bk, bv);
    attn_mma<<<dim3(8, 64), 256, ATTN_SMEM_BYTES>>>(mask);
    gemm_out<<<dim3(8, 32), 256, GEMM_SMEM>>>(bo, out);
}

// round 12
// speedup vs baseline: 1.5290x; 1.0490x over previous
#include <cuda_runtime.h>
#include <cuda_fp16.h>
#include <math.h>
#include <cstdint>

#define SEQ    512
#define DQ     1024
#define MTOK   4096
#define SCALE  0.044194173824159216f   // 1/sqrt(512)
#define SCALEL2 0.06375898748054754f   // SCALE * log2(e)
#define NEG    -4.4194174e18f          // huge negative (log2 domain; ex2 -> 0)

// Scratch (device globals; no allocation allowed)
// g_x*, g_w*, g_ao: LAYER-1 PERMUTED fp16 (uint order [0,4,1,5,2,6,3,7] per 16-half group)
// g_q/g_k/g_v: row-major fp16. g_mb: packed mask bits.
__device__ __half g_xq[MTOK * DQ];
__device__ __half g_xk[MTOK * DQ];
__device__ __half g_xv[MTOK * DQ];
__device__ __half g_wq[DQ * DQ];
__device__ __half g_wk[DQ * DQ];
__device__ __half g_wv[DQ * DQ];
__device__ __half g_wo[DQ * DQ];
__device__ __half g_q [MTOK * DQ];
__device__ __half g_k [MTOK * DQ];
__device__ __half g_v [MTOK * DQ];
__device__ __half g_ao[MTOK * DQ];
__device__ unsigned g_mb[MTOK * 16];   // [n*512+ql][w]: bit kl%32 of word kl/32

// ---------------------------------------------------------------------------
// helpers
// ---------------------------------------------------------------------------
__device__ __forceinline__ void mma_f16(float* c, const unsigned* a, const unsigned* b) {
    asm volatile(
        "mma.sync.aligned.m16n8k16.row.col.f32.f16.f16.f32 "
        "{%0,%1,%2,%3}, {%4,%5,%6,%7}, {%8,%9}, {%0,%1,%2,%3};\n"
        : "+f"(c[0]), "+f"(c[1]), "+f"(c[2]), "+f"(c[3])
        : "r"(a[0]), "r"(a[1]), "r"(a[2]), "r"(a[3]), "r"(b[0]), "r"(b[1]));
}
__device__ __forceinline__ uint32_t smem_u32(const void* p) {
    uint32_t a;
    asm("{ .reg .u64 t; cvta.to.shared.u64 t, %1; cvt.u32.u64 %0, t; }" : "=r"(a) : "l"(p));
    return a;
}
__device__ __forceinline__ void cp16(uint32_t s, const void* g) {
    asm volatile("cp.async.cg.shared.global [%0], [%1], 16;" :: "r"(s), "l"(g));
}
#define CP_COMMIT() asm volatile("cp.async.commit_group;" ::: "memory")
#define CP_WAIT0()  asm volatile("cp.async.wait_group 0;" ::: "memory")
__device__ __forceinline__ unsigned pack_h2(float x, float y) {
    __half2 h = __floats2half2_rn(x, y);
    return *(unsigned*)&h;
}
__device__ __forceinline__ float ex2f(float x) {
    float y; asm("ex2.approx.f32 %0, %1;" : "=f"(y) : "f"(x)); return y;
}

// ---------------------------------------------------------------------------
// f32 -> f16 conversion + layer-1 permutation + mask bit-packing, one pass.
// Tasks: [0, 1048576) 16-half groups; [1048576, 1114112) mask words.
// ---------------------------------------------------------------------------
__global__ __launch_bounds__(256) void cvt_kernel(
    const float* __restrict__ q, const float* __restrict__ k, const float* __restrict__ v,
    const float* __restrict__ wv, const float* __restrict__ wk,
    const float* __restrict__ wq, const float* __restrict__ wo,
    const int* __restrict__ mask)
{
    const long stride = (long)gridDim.x * blockDim.x;
    for (long g = (long)blockIdx.x * blockDim.x + threadIdx.x; g < 1114112; g += stride) {
        if (g < 1048576) {
            const float* src; __half* dst; long goff;
            if (g < 786432) {
                int which = (int)(g >> 18);
                goff = g & 262143;
                src = which == 0 ? q : which == 1 ? k : v;
                dst = which == 0 ? g_xq : which == 1 ? g_xk : g_xv;
            } else {
                long j = g - 786432;
                int which = (int)(j >> 16);
                goff = j & 65535;
                src = which == 0 ? wv : which == 1 ? wk : which == 2 ? wq : wo;
                dst = which == 0 ? g_wv : which == 1 ? g_wk : which == 2 ? g_wq : g_wo;
            }
            const float4* s4 = (const float4*)(src + goff * 16);
            float4 f0 = s4[0], f1 = s4[1], f2 = s4[2], f3 = s4[3];
            uint4 o0, o1;
            o0.x = pack_h2(f0.x, f0.y);  o0.y = pack_h2(f2.x, f2.y);
            o0.z = pack_h2(f0.z, f0.w);  o0.w = pack_h2(f2.z, f2.w);
            o1.x = pack_h2(f1.x, f1.y);  o1.y = pack_h2(f3.x, f3.y);
            o1.z = pack_h2(f1.z, f1.w);  o1.w = pack_h2(f3.z, f3.w);
            uint4* d4 = (uint4*)(dst + goff * 16);
            d4[0] = o0;
            d4[1] = o1;
        } else {
            long w = g - 1048576;
            long row = w >> 4;            // n*512 + ql
            int word = (int)(w & 15);
            const uint4* p = (const uint4*)(mask + row * 512 + word * 32);
            unsigned bits = 0;
            #pragma unroll
            for (int i = 0; i < 8; i++) {
                uint4 vv = p[i];
                bits |= (vv.x != 0u ? 1u : 0u) << (i * 4 + 0);
                bits |= (vv.y != 0u ? 1u : 0u) << (i * 4 + 1);
                bits |= (vv.z != 0u ? 1u : 0u) << (i * 4 + 2);
                bits |= (vv.w != 0u ? 1u : 0u) << (i * 4 + 3);
            }
            g_mb[row * 16 + word] = bits;
        }
    }
}

// ---------------------------------------------------------------------------
// Pipelined fp16 GEMM (exact R11): C = A @ W^T + bias.
// ---------------------------------------------------------------------------
#define GSTG  4096                     // uints per tile stage (128*32)
#define GEMM_SMEM (6 * GSTG * 4)       // 98304 bytes

template<bool HALF_OUT>
__device__ __forceinline__ void gemm_body(
    const __half* __restrict__ A, const __half* __restrict__ W,
    const float* __restrict__ bias, void* Cv)
{
    extern __shared__ __align__(16) unsigned sm[];
    const int tid = threadIdx.x;
    const int warp = tid >> 5, lane = tid & 31;
    const int gid = lane >> 2, tig = lane & 3;
    const int wm = warp >> 2, wn = warp & 3;
    const int m0 = blockIdx.y * 128, n0 = blockIdx.x * 128;
    const uint32_t smb = smem_u32(sm);

    float c[4][4][4] = {};

    auto issue = [&](int stage) {
        const int buf = stage % 3;
        const long k0 = (long)stage * 64;
        const uint32_t ab = smb + buf * (GSTG * 4);
        const uint32_t bb = smb + 3 * (GSTG * 4) + buf * (GSTG * 4);
        #pragma unroll
        for (int u = 0; u < 4; u++) {
            int chunk = tid + 256 * u;
            int row = chunk >> 3, qq = chunk & 7;
            uint32_t doff = (row * 32 + 4 * (qq ^ ((row & 3) << 1))) * 4;
            cp16(ab + doff, &A[(long)(m0 + row) * 1024 + k0 + qq * 8]);
        }
        #pragma unroll
        for (int u = 0; u < 4; u++) {
            int chunk = tid + 256 * u;
            int row = chunk >> 3, qq = chunk & 7;
            uint32_t doff = (row * 32 + 4 * (qq ^ ((row & 3) << 1))) * 4;
            cp16(bb + doff, &W[(long)(n0 + row) * 1024 + k0 + qq * 8]);
        }
        CP_COMMIT();
    };

    issue(0);
    issue(1);

    #pragma unroll
    for (int ch = 0; ch < 16; ch++) {
        if (ch < 14) asm volatile("cp.async.wait_group 1;" ::: "memory");
        else         asm volatile("cp.async.wait_group 0;" ::: "memory");
        __syncthreads();
        if (ch + 2 < 16) issue(ch + 2);

        unsigned* Ab = sm + (ch % 3) * GSTG;
        unsigned* Bb = sm + 3 * GSTG + (ch % 3) * GSTG;
        #pragma unroll
        for (int s = 0; s < 4; s++) {
            const int po = 8 * (s ^ (gid & 3)) + 2 * tig;
            unsigned a[4][4], b[4][2];
            #pragma unroll
            for (int ma = 0; ma < 4; ma++) {
                int r = wm * 64 + ma * 16 + gid;
                uint2 A1 = *(const uint2*)&Ab[r * 32 + po];
                uint2 A2 = *(const uint2*)&Ab[(r + 8) * 32 + po];
                a[ma][0] = A1.x; a[ma][1] = A2.x; a[ma][2] = A1.y; a[ma][3] = A2.y;
            }
            #pragma unroll
            for (int nb = 0; nb < 4; nb++) {
                int cc = wn * 32 + nb * 8 + gid;
                uint2 B1 = *(const uint2*)&Bb[cc * 32 + po];
                b[nb][0] = B1.x; b[nb][1] = B1.y;
            }
            #pragma unroll
            for (int ma = 0; ma < 4; ma++)
                #pragma unroll
                for (int nb = 0; nb < 4; nb++)
                    mma_f16(c[ma][nb], a[ma], b[nb]);
        }
    }

    #pragma unroll
    for (int ma = 0; ma < 4; ma++) {
        int r = m0 + wm * 64 + ma * 16 + gid;
        #pragma unroll
        for (int nb = 0; nb < 4; nb++) {
            int col = n0 + wn * 32 + nb * 8 + 2 * tig;
            float b0 = bias[col], b1 = bias[col + 1];
            if (HALF_OUT) {
                __half* C = (__half*)Cv;
                __half2 v0 = __floats2half2_rn(c[ma][nb][0] + b0, c[ma][nb][1] + b1);
                __half2 v1 = __floats2half2_rn(c[ma][nb][2] + b0, c[ma][nb][3] + b1);
                *(__half2*)&C[(long)r * 1024 + col]       = v0;
                *(__half2*)&C[(long)(r + 8) * 1024 + col] = v1;
            } else {
                float* C = (float*)Cv;
                *(float2*)&C[(long)r * 1024 + col] =
                    make_float2(c[ma][nb][0] + b0, c[ma][nb][1] + b1);
                *(float2*)&C[(long)(r + 8) * 1024 + col] =
                    make_float2(c[ma][nb][2] + b0, c[ma][nb][3] + b1);
            }
        }
    }
}

__global__ __launch_bounds__(256, 2) void gemm_qkv(
    const float* __restrict__ bq, const float* __restrict__ bk, const float* __restrict__ bv)
{
    if (blockIdx.z == 0)      gemm_body<true>(g_xq, g_wq, bq, g_q);
    else if (blockIdx.z == 1) gemm_body<true>(g_xk, g_wk, bk, g_k);
    else                      gemm_body<true>(g_xv, g_wv, bv, g_v);
}

__global__ __launch_bounds__(256, 2) void gemm_out(
    const float* __restrict__ bo, float* __restrict__ C)
{
    gemm_body<false>(g_ao, g_wo, bo, C);
}

// ---------------------------------------------------------------------------
// Flash attention: fp16 mma, register P, cp.async K double buffering,
// register-prefetched V, CF Vt, PACKED mask bits (staged once), log2-domain
// softmax (log2e folded into Q scale; raw ex2).
// Epilogue writes g_ao LAYER-1 PERMUTED (consumed only by gemm_out).
// ---------------------------------------------------------------------------
#define ATTN_SMEM_BYTES ((2*64*36 + 32*72 + 128*36 + 64*16) * 4)   // 50176

__global__ __launch_bounds__(256, 2) void attn_mma(const int* __restrict__ mask_unused)
{
    extern __shared__ __align__(16) unsigned smA[];
    unsigned* Ks  = smA;                   // 2 bufs [64][36] half2
    unsigned* Vt  = Ks + 2 * 64 * 36;      // [c2:32][72] half2 pairs-along-c
    unsigned* Qs  = Vt + 32 * 72;          // [row:128][36] half2
    unsigned* Msm = Qs + 128 * 36;         // [ql:64][16] packed mask words

    const int nh = blockIdx.y, n = nh >> 3, h = nh & 7;
    const int bx = blockIdx.x;
    const int tid = threadIdx.x;
    const int warp = tid >> 5, lane = tid & 31;
    const int gid = lane >> 2, tig = lane & 3;
    const int r0 = warp * 16 + gid, r1 = r0 + 8;
    const uint32_t ks_smb = smem_u32(Ks);

    const __half2 sc2 = __floats2half2_rn(SCALEL2, SCALEL2);

    auto issue_tile = [&](int t) {
        const int buf = t & 1;
        const uint32_t kb = ks_smb + buf * (64 * 36 * 4);
        #pragma unroll
        for (int u = 0; u < 2; u++) {
            int chunk = tid + 256 * u;
            int cc = chunk >> 3, qq = chunk & 7;
            int cg = t * 64 + cc;
            int kl = cg >> 1, y = cg & 1;
            cp16(kb + (cc * 36 + qq * 4) * 4,
                 &g_k[(long)(n * SEQ + kl) * DQ + y * 512 + h * 64 + qq * 8]);
        }
        CP_COMMIT();
    };

    // Stage packed mask rows for this CTA: 64 rows x 16 words (one uint4/thread)
    {
        int row = tid >> 2, c = (tid & 3) * 4;
        uint4 mw = *(const uint4*)&g_mb[((long)(n * SEQ + bx * 64 + row)) * 16 + c];
        *(uint4*)&Msm[row * 16 + c] = mw;
    }

    // Stage Q (pre-scaled by SCALE*log2e, half2)
    #pragma unroll
    for (int u = 0; u < 8; u++) {
        int idx = tid + 256 * u;
        int row = idx >> 4, d = (idx & 15) * 4;
        int rg = bx * 128 + row;
        int ql = rg >> 1, x = rg & 1;
        uint2 v = *(const uint2*)&g_q[(long)(n * SEQ + ql) * DQ + x * 512 + h * 64 + d];
        __half2 h0 = __hmul2(*(__half2*)&v.x, sc2);
        __half2 h1 = __hmul2(*(__half2*)&v.y, sc2);
        Qs[row * 36 + d / 2]     = *(unsigned*)&h0;
        Qs[row * 36 + d / 2 + 1] = *(unsigned*)&h1;
    }
    issue_tile(0);
    __syncthreads();
    unsigned q[4][4];
    #pragma unroll
    for (int s = 0; s < 4; s++) {
        q[s][0] = Qs[r0 * 36 + 8 * s + tig];
        q[s][1] = Qs[r1 * 36 + 8 * s + tig];
        q[s][2] = Qs[r0 * 36 + 8 * s + tig + 4];
        q[s][3] = Qs[r1 * 36 + 8 * s + tig + 4];
    }

    float o[8][4] = {};
    float m0 = -INFINITY, m1 = -INFINITY, l0 = 0.f, l1 = 0.f;
    const int qll0 = r0 >> 1, qll1 = qll0 + 4;

    const int v_c2 = tid >> 4;
    const int v_d4 = (tid & 15) * 4;

    for (int t = 0; t < 16; t++) {
        CP_WAIT0();
        __syncthreads();
        if (t + 1 < 16) issue_tile(t + 1);

        uint2 vlo[2], vhi[2];
        #pragma unroll
        for (int u = 0; u < 2; u++) {
            int kl = t * 32 + v_c2 + 16 * u;
            long base = (long)(n * SEQ + kl) * DQ + h * 64 + v_d4;
            vlo[u] = *(const uint2*)&g_v[base];
            vhi[u] = *(const uint2*)&g_v[base + 512];
        }

        const unsigned* Kb = Ks + (t & 1) * (64 * 36);
        const unsigned mb0 = Msm[qll0 * 16 + t];
        const unsigned mb1 = Msm[qll1 * 16 + t];

        float s[8][4] = {};
        #pragma unroll
        for (int ks = 0; ks < 4; ks++) {
            unsigned bb[8][2];
            #pragma unroll
            for (int j = 0; j < 8; j++) {
                bb[j][0] = Kb[(8 * j + gid) * 36 + 8 * ks + tig];
                bb[j][1] = Kb[(8 * j + gid) * 36 + 8 * ks + tig + 4];
            }
            #pragma unroll
            for (int j = 0; j < 8; j++)
                mma_f16(s[j], q[ks], bb[j]);
        }

        // Mask (packed bits) + online softmax in log2 domain
        float mx0 = m0, mx1 = m1;
        #pragma unroll
        for (int j = 0; j < 8; j++) {
            int klc = 4 * j + tig;
            bool k0m = (mb0 >> klc) & 1u;
            bool k1m = (mb1 >> klc) & 1u;
            s[j][0] = k0m ? s[j][0] : NEG;
            s[j][1] = k0m ? s[j][1] : NEG;
            s[j][2] = k1m ? s[j][2] : NEG;
            s[j][3] = k1m ? s[j][3] : NEG;
            mx0 = fmaxf(mx0, fmaxf(s[j][0], s[j][1]));
            mx1 = fmaxf(mx1, fmaxf(s[j][2], s[j][3]));
        }
        mx0 = fmaxf(mx0, __shfl_xor_sync(0xffffffffu, mx0, 1));
        mx0 = fmaxf(mx0, __shfl_xor_sync(0xffffffffu, mx0, 2));
        mx1 = fmaxf(mx1, __shfl_xor_sync(0xffffffffu, mx1, 1));
        mx1 = fmaxf(mx1, __shfl_xor_sync(0xffffffffu, mx1, 2));
        float a0 = ex2f(m0 - mx0), a1 = ex2f(m1 - mx1);
        float sum0 = 0.f, sum1 = 0.f;
        #pragma unroll
        for (int j = 0; j < 8; j++) {
            s[j][0] = ex2f(s[j][0] - mx0);
            s[j][1] = ex2f(s[j][1] - mx0);
            s[j][2] = ex2f(s[j][2] - mx1);
            s[j][3] = ex2f(s[j][3] - mx1);
            sum0 += s[j][0] + s[j][1];
            sum1 += s[j][2] + s[j][3];
        }
        sum0 += __shfl_xor_sync(0xffffffffu, sum0, 1);
        sum0 += __shfl_xor_sync(0xffffffffu, sum0, 2);
        sum1 += __shfl_xor_sync(0xffffffffu, sum1, 1);
        sum1 += __shfl_xor_sync(0xffffffffu, sum1, 2);
        l0 = l0 * a0 + sum0; l1 = l1 * a1 + sum1;
        m0 = mx0; m1 = mx1;
        #pragma unroll
        for (int j = 0; j < 8; j++) {
            o[j][0] *= a0; o[j][1] *= a0; o[j][2] *= a1; o[j][3] *= a1;
        }

        #pragma unroll
        for (int u = 0; u < 2; u++) {
            __half2 l0h = *(__half2*)&vlo[u].x, l1h = *(__half2*)&vlo[u].y;
            __half2 h0h = *(__half2*)&vhi[u].x, h1h = *(__half2*)&vhi[u].y;
            __half2 p0 = __halves2half2(__low2half(l0h),  __low2half(h0h));
            __half2 p1 = __halves2half2(__high2half(l0h), __high2half(h0h));
            __half2 p2 = __halves2half2(__low2half(l1h),  __low2half(h1h));
            __half2 p3 = __halves2half2(__high2half(l1h), __high2half(h1h));
            *(uint4*)&Vt[(v_c2 + 16 * u) * 72 + v_d4] = make_uint4(
                *(unsigned*)&p0, *(unsigned*)&p1, *(unsigned*)&p2, *(unsigned*)&p3);
        }
        __syncthreads();

        #pragma unroll
        for (int ks = 0; ks < 4; ks++) {
            unsigned a[4];
            a[0] = pack_h2(s[2 * ks][0],     s[2 * ks][1]);
            a[1] = pack_h2(s[2 * ks][2],     s[2 * ks][3]);
            a[2] = pack_h2(s[2 * ks + 1][0], s[2 * ks + 1][1]);
            a[3] = pack_h2(s[2 * ks + 1][2], s[2 * ks + 1][3]);
            unsigned bb[8][2];
            #pragma unroll
            for (int j = 0; j < 8; j++) {
                bb[j][0] = Vt[(8 * ks + tig) * 72 + 8 * j + gid];
                bb[j][1] = Vt[(8 * ks + tig + 4) * 72 + 8 * j + gid];
            }
            #pragma unroll
            for (int j = 0; j < 8; j++)
                mma_f16(o[j], a, bb[j]);
        }
    }

    // Normalize + store g_ao LAYER-1 PERMUTED
    float inv0 = 1.f / l0, inv1 = 1.f / l1;
    int rg0 = bx * 128 + r0, rg1 = rg0 + 8;
    int ql0 = rg0 >> 1, x0 = rg0 & 1;
    int ql1 = rg1 >> 1, x1 = rg1 & 1;
    __half* out0 = &g_ao[(long)(n * SEQ + ql0) * DQ + x0 * 512 + h * 64];
    __half* out1 = &g_ao[(long)(n * SEQ + ql1) * DQ + x1 * 512 + h * 64];
    #pragma unroll
    for (int j = 0; j < 8; j++) {
        int off = 16 * (j >> 1) + 4 * tig + 2 * (j & 1);
        *(__half2*)&out0[off] = __floats2half2_rn(o[j][0] * inv0, o[j][1] * inv0);
        *(__half2*)&out1[off] = __floats2half2_rn(o[j][2] * inv1, o[j][3] * inv1);
    }
}

// ---------------------------------------------------------------------------
extern "C" void kernel_launch(void* const* d_in, const int* in_sizes, int n_in,
                              void* d_out, int out_size)
{
    const float* query = (const float*)d_in[0];
    const float* key   = (const float*)d_in[1];
    const float* value = (const float*)d_in[2];
    const int*   mask  = (const int*)  d_in[3];
    const float* Wv    = (const float*)d_in[4];
    const float* bv    = (const float*)d_in[5];
    const float* Wk    = (const float*)d_in[6];
    const float* bk    = (const float*)d_in[7];
    const float* Wq    = (const float*)d_in[8];
    const float* bq    = (const float*)d_in[9];
    const float* Wo    = (const float*)d_in[10];
    const float* bo    = (const float*)d_in[11];
    float* out = (float*)d_out;

    static bool attr_set = false;
    if (!attr_set) {
        cudaFuncSetAttribute(attn_mma, cudaFuncAttributeMaxDynamicSharedMemorySize,
                             ATTN_SMEM_BYTES);
        cudaFuncSetAttribute(gemm_qkv, cudaFuncAttributeMaxDynamicSharedMemorySize,
                             GEMM_SMEM);
        cudaFuncSetAttribute(gemm_out, cudaFuncAttributeMaxDynamicSharedMemorySize,
                             GEMM_SMEM);
        attr_set = true;
    }

    cvt_kernel<<<2048, 256>>>(query, key, value, Wv, Wk, Wq, Wo, mask);
    gemm_qkv<<<dim3(8, 32, 3), 256, GEMM_SMEM>>>(bq, bk, bv);
    attn_mma<<<dim3(8, 64), 256, ATTN_SMEM_BYTES>>>(mask);
    gemm_out<<<dim3(8, 32), 256, GEMM_SMEM>>>(bo, out);
}